// round 2
// baseline (speedup 1.0000x reference)
#include <cuda_runtime.h>
#include <math.h>

#define NN 50000
#define NE 800000
#define KM 193          // 1 + 2*64 + 64 message-MLP input dim
#define MS 68           // padded msg_T row stride (floats), 16B aligned, reduces STS conflicts

// scratch (static device globals: no allocation anywhere)
__device__ float g_agg[(size_t)NN * 64];
__device__ float g_cnt[NN];

__global__ void zero_k() {
    int i = blockIdx.x * blockDim.x + threadIdx.x;
    int stride = gridDim.x * blockDim.x;
    for (int j = i; j < NN * 64; j += stride) g_agg[j] = 0.0f;
    for (int j = i; j < NN; j += stride) g_cnt[j] = 0.0f;
}

__device__ __forceinline__ float softplus_f(float v) {
    // stable: max(v,0) + log1p(exp(-|v|))  == jax.nn.softplus
    return fmaxf(v, 0.0f) + log1pf(expf(-fabsf(v)));
}

extern __shared__ float smem[];

// Block: 256 threads. Tile: 64 edges x 64 msg-cols, k = 193.
// smem: W_msg [193*64] + feat_T [193*64] (reused as padded msg_T [64 x MS]) + dst[64]
__global__ __launch_bounds__(256, 2) void edge_k(
    const float* __restrict__ x,
    const int* __restrict__ ei,            // [2, NE] int32 (JAX x64 disabled downcasts int64)
    const float* __restrict__ ea,
    const float* __restrict__ rr,          // [NE, 2]
    const float* __restrict__ dinit,       // [NE, 1]
    const float* __restrict__ Wmsg,        // [193, 64]
    const float* __restrict__ bmsg,        // [64]
    const float* __restrict__ Wedge,       // [64, 64]
    const float* __restrict__ bedge,       // [64]
    float* __restrict__ out)
{
    float* W_s  = smem;                 // 193*64
    float* feat = smem + KM * 64;       // 193*64  (feat_T[k][e]; later msg_T[c][e] stride MS)
    int*   dst_s = (int*)(smem + 2 * KM * 64);   // 64 ints

    float* out_edge = out + (size_t)NN * 64;
    float* out_msg  = out + (size_t)NN * 64 + (size_t)NE * 64;
    float* out_str  = out + (size_t)NN * 64 + 2 * (size_t)NE * 64;

    const int tx = threadIdx.x;

    // stage W_msg once per block (L2-resident, amortized over ~40 tiles)
    for (int i = tx; i < KM * 64 / 4; i += 256)
        ((float4*)W_s)[i] = ((const float4*)Wmsg)[i];

    const int c_id = tx & 15, e_id = tx >> 4;
    const int c0 = c_id * 4, e0 = e_id * 4;
    const float4 bm = ((const float4*)bmsg)[c_id];
    const float4 be = ((const float4*)bedge)[c_id];

    const int es = tx >> 2, part = tx & 3;   // staging role: 4 threads per edge row

    for (int tile = blockIdx.x; tile < NE / 64; tile += gridDim.x) {
        __syncthreads();   // protect feat reuse across iterations (and W_s on first)

        // ---------- stage feat_T[k][e]: [x_src | x_dst | strain | edge_attr] ----------
        size_t eg = (size_t)tile * 64 + es;
        int src = ei[eg];
        int dst = ei[NE + eg];
        const float4* xs = (const float4*)(x + (size_t)src * 64) + part * 4;
        const float4* xd = (const float4*)(x + (size_t)dst * 64) + part * 4;
        const float4* ep = (const float4*)(ea + eg * 64) + part * 4;
        #pragma unroll
        for (int i = 0; i < 4; i++) {
            int kb = part * 16 + i * 4;
            float4 v = xs[i];
            feat[(kb + 0) * 64 + es] = v.x; feat[(kb + 1) * 64 + es] = v.y;
            feat[(kb + 2) * 64 + es] = v.z; feat[(kb + 3) * 64 + es] = v.w;
            float4 w = xd[i];
            feat[(64 + kb + 0) * 64 + es] = w.x; feat[(64 + kb + 1) * 64 + es] = w.y;
            feat[(64 + kb + 2) * 64 + es] = w.z; feat[(64 + kb + 3) * 64 + es] = w.w;
            float4 u = ep[i];
            feat[(129 + kb + 0) * 64 + es] = u.x; feat[(129 + kb + 1) * 64 + es] = u.y;
            feat[(129 + kb + 2) * 64 + es] = u.z; feat[(129 + kb + 3) * 64 + es] = u.w;
        }
        if (part == 0) {
            float r0 = rr[eg * 2 + 0], r1 = rr[eg * 2 + 1];
            float d = sqrtf(r0 * r0 + r1 * r1);
            float di = dinit[eg];
            float s = (d - di) / di;
            feat[128 * 64 + es] = s;
            out_str[eg] = s;
            dst_s[es] = dst;
            atomicAdd(&g_cnt[dst], 1.0f);
        }
        __syncthreads();

        // ---------- GEMM1: pre = feat @ Wmsg ----------
        float acc[4][4];
        #pragma unroll
        for (int i = 0; i < 4; i++)
            #pragma unroll
            for (int j = 0; j < 4; j++) acc[i][j] = 0.0f;

        #pragma unroll 4
        for (int k = 0; k < KM; k++) {
            float4 f = *(const float4*)(feat + k * 64 + e0);
            float4 w = *(const float4*)(W_s  + k * 64 + c0);
            acc[0][0] += f.x * w.x; acc[0][1] += f.x * w.y; acc[0][2] += f.x * w.z; acc[0][3] += f.x * w.w;
            acc[1][0] += f.y * w.x; acc[1][1] += f.y * w.y; acc[1][2] += f.y * w.z; acc[1][3] += f.y * w.w;
            acc[2][0] += f.z * w.x; acc[2][1] += f.z * w.y; acc[2][2] += f.z * w.z; acc[2][3] += f.z * w.w;
            acc[3][0] += f.w * w.x; acc[3][1] += f.w * w.y; acc[3][2] += f.w * w.z; acc[3][3] += f.w * w.w;
        }

        // ---------- softplus + bias, write msg, aggregate ----------
        float m[4][4];
        #pragma unroll
        for (int i = 0; i < 4; i++) {
            m[i][0] = softplus_f(acc[i][0] + bm.x);
            m[i][1] = softplus_f(acc[i][1] + bm.y);
            m[i][2] = softplus_f(acc[i][2] + bm.z);
            m[i][3] = softplus_f(acc[i][3] + bm.w);
        }
        size_t base = (size_t)tile * 64 * 64;
        #pragma unroll
        for (int i = 0; i < 4; i++) {
            *(float4*)(out_msg + base + (size_t)(e0 + i) * 64 + c0) =
                make_float4(m[i][0], m[i][1], m[i][2], m[i][3]);
            int d = dst_s[e0 + i];
            float* ap = g_agg + (size_t)d * 64 + c0;
            atomicAdd(ap + 0, m[i][0]); atomicAdd(ap + 1, m[i][1]);
            atomicAdd(ap + 2, m[i][2]); atomicAdd(ap + 3, m[i][3]);
        }

        __syncthreads();   // all gemm1 reads of feat done before overwrite
        // msg_T[c][e] with padded stride MS (vector store along e)
        #pragma unroll
        for (int j = 0; j < 4; j++)
            *(float4*)(feat + (size_t)(c0 + j) * MS + e0) =
                make_float4(m[0][j], m[1][j], m[2][j], m[3][j]);
        __syncthreads();

        // ---------- GEMM2: edge_new = msg @ Wedge + b ----------
        float a2[4][4];
        #pragma unroll
        for (int i = 0; i < 4; i++)
            #pragma unroll
            for (int j = 0; j < 4; j++) a2[i][j] = 0.0f;

        #pragma unroll 4
        for (int k = 0; k < 64; k++) {
            float4 f = *(const float4*)(feat + (size_t)k * MS + e0);
            float4 w = __ldg((const float4*)(Wedge + (size_t)k * 64 + c0));
            a2[0][0] += f.x * w.x; a2[0][1] += f.x * w.y; a2[0][2] += f.x * w.z; a2[0][3] += f.x * w.w;
            a2[1][0] += f.y * w.x; a2[1][1] += f.y * w.y; a2[1][2] += f.y * w.z; a2[1][3] += f.y * w.w;
            a2[2][0] += f.z * w.x; a2[2][1] += f.z * w.y; a2[2][2] += f.z * w.z; a2[2][3] += f.z * w.w;
            a2[3][0] += f.w * w.x; a2[3][1] += f.w * w.y; a2[3][2] += f.w * w.z; a2[3][3] += f.w * w.w;
        }
        #pragma unroll
        for (int i = 0; i < 4; i++) {
            *(float4*)(out_edge + base + (size_t)(e0 + i) * 64 + c0) =
                make_float4(a2[i][0] + be.x, a2[i][1] + be.y, a2[i][2] + be.z, a2[i][3] + be.w);
        }
    }
}

// Node update: x_new = [x | agg/max(cnt,1)] @ W_upd + b_upd. Warp per node.
__global__ __launch_bounds__(256) void node_k(
    const float* __restrict__ x,
    const float* __restrict__ Wupd,    // [128, 64]
    const float* __restrict__ bupd,    // [64]
    float* __restrict__ out_x)
{
    __shared__ float W_s[128 * 64];
    __shared__ float f_s[8][128];

    int tx = threadIdx.x;
    for (int i = tx; i < 128 * 64 / 4; i += 256)
        ((float4*)W_s)[i] = ((const float4*)Wupd)[i];
    __syncthreads();

    int warp = tx >> 5, lane = tx & 31;
    int c0 = lane * 2;
    float b0 = bupd[c0], b1 = bupd[c0 + 1];

    for (int node = blockIdx.x * 8 + warp; node < NN; node += gridDim.x * 8) {
        float inv = 1.0f / fmaxf(g_cnt[node], 1.0f);
        const float* xr = x + (size_t)node * 64;
        const float* ar = g_agg + (size_t)node * 64;
        f_s[warp][lane]       = xr[lane];
        f_s[warp][lane + 32]  = xr[lane + 32];
        f_s[warp][64 + lane]  = ar[lane] * inv;
        f_s[warp][96 + lane]  = ar[lane + 32] * inv;
        __syncwarp();

        float a0 = 0.0f, a1 = 0.0f;
        #pragma unroll 8
        for (int k = 0; k < 128; k++) {
            float f = f_s[warp][k];
            float2 w = *(const float2*)(W_s + k * 64 + c0);
            a0 += f * w.x; a1 += f * w.y;
        }
        out_x[(size_t)node * 64 + c0]     = a0 + b0;
        out_x[(size_t)node * 64 + c0 + 1] = a1 + b1;
        __syncwarp();
    }
}

extern "C" void kernel_launch(void* const* d_in, const int* in_sizes, int n_in,
                              void* d_out, int out_size) {
    const float* x     = (const float*)d_in[0];
    const int*   ei    = (const int*)d_in[1];
    const float* ea    = (const float*)d_in[2];
    const float* rr    = (const float*)d_in[3];
    const float* dinit = (const float*)d_in[4];
    const float* Wmsg  = (const float*)d_in[5];
    const float* bmsg  = (const float*)d_in[6];
    const float* Wupd  = (const float*)d_in[7];
    const float* bupd  = (const float*)d_in[8];
    const float* Wedge = (const float*)d_in[9];
    const float* bedge = (const float*)d_in[10];
    float* out = (float*)d_out;

    (void)in_sizes; (void)n_in; (void)out_size;

    const int SMEM = (2 * KM * 64) * 4 + 64 * 4;   // 99,072 B
    cudaFuncSetAttribute(edge_k, cudaFuncAttributeMaxDynamicSharedMemorySize, SMEM);

    zero_k<<<512, 256>>>();
    edge_k<<<304, 256, SMEM>>>(x, ei, ea, rr, dinit, Wmsg, bmsg, Wedge, bedge, out);
    node_k<<<304, 256>>>(x, Wupd, bupd, out);
}

// round 4
// speedup vs baseline: 1.5544x; 1.5544x over previous
#include <cuda_runtime.h>
#include <math.h>

#define NN 50000
#define NE 800000
#define MS 68           // padded msg_T row stride (floats)

// scratch (static device globals: no allocation anywhere)
__device__ float g_agg[(size_t)NN * 64];
__device__ float g_cnt[NN];
__device__ float g_P1[(size_t)NN * 64];
__device__ float g_P2[(size_t)NN * 64];

__global__ void zero_k() {
    int i = blockIdx.x * blockDim.x + threadIdx.x;
    int stride = gridDim.x * blockDim.x;
    for (int j = i; j < NN * 64; j += stride) g_agg[j] = 0.0f;
    for (int j = i; j < NN; j += stride) g_cnt[j] = 0.0f;
}

// P1 = x @ Wmsg[0:64], P2 = x @ Wmsg[64:128]   (per-node precompute, 0.8G MACs)
__global__ __launch_bounds__(256) void prep_k(const float* __restrict__ x,
                                              const float* __restrict__ Wmsg) {
    __shared__ float W_s[128 * 64];
    __shared__ float xs[8][64];
    int tx = threadIdx.x;
    for (int i = tx; i < 128 * 64 / 4; i += 256)
        ((float4*)W_s)[i] = ((const float4*)Wmsg)[i];
    __syncthreads();
    int warp = tx >> 5, lane = tx & 31;
    for (int node = blockIdx.x * 8 + warp; node < NN; node += gridDim.x * 8) {
        xs[warp][lane]      = x[(size_t)node * 64 + lane];
        xs[warp][lane + 32] = x[(size_t)node * 64 + lane + 32];
        __syncwarp();
        float a1 = 0, b1 = 0, a2 = 0, b2 = 0;
        #pragma unroll 8
        for (int k = 0; k < 64; k++) {
            float f = xs[warp][k];
            float2 w1 = *(const float2*)(W_s + k * 64 + lane * 2);
            float2 w2 = *(const float2*)(W_s + (64 + k) * 64 + lane * 2);
            a1 += f * w1.x; b1 += f * w1.y;
            a2 += f * w2.x; b2 += f * w2.y;
        }
        g_P1[(size_t)node * 64 + lane * 2]     = a1;
        g_P1[(size_t)node * 64 + lane * 2 + 1] = b1;
        g_P2[(size_t)node * 64 + lane * 2]     = a2;
        g_P2[(size_t)node * 64 + lane * 2 + 1] = b2;
        __syncwarp();
    }
}

__device__ __forceinline__ float softplus_f(float v) {
    // stable: max(v,0) + log1p(exp(-|v|))  == jax.nn.softplus
    return fmaxf(v, 0.0f) + log1pf(expf(-fabsf(v)));
}

extern __shared__ float smem[];

// Block: 256 threads. Tile: 64 edges x 64 cols. GEMM1 k=64 (ea@W3), GEMM2 k=64 (msg@We).
// smem floats: W3[4096] | We[4096] | buf[4352] (ea_T stride 64, then msg_T stride 68)
//              | ws[64] bm[64] be[64] | src[64] dst[64] strain[64]
#define O_W3   0
#define O_WE   4096
#define O_BUF  8192
#define O_WS   12544
#define O_BM   12608
#define O_BE   12672
#define O_SRC  12736
#define O_DST  12800
#define O_STR  12864
#define SMEM_FLOATS 12928      // 51,712 bytes -> 4 CTAs/SM

__global__ __launch_bounds__(256, 4) void edge_k(
    const int* __restrict__ ei,            // [2, NE] int32
    const float* __restrict__ ea,
    const float* __restrict__ rr,          // [NE, 2]
    const float* __restrict__ dinit,       // [NE, 1]
    const float* __restrict__ Wmsg,        // [193, 64]
    const float* __restrict__ bmsg,
    const float* __restrict__ Wedge,       // [64, 64]
    const float* __restrict__ bedge,
    float* __restrict__ out)
{
    float* W3_s = smem + O_W3;
    float* We_s = smem + O_WE;
    float* buf  = smem + O_BUF;
    float* ws_s = smem + O_WS;
    float* bm_s = smem + O_BM;
    float* be_s = smem + O_BE;
    int*   src_s = (int*)(smem + O_SRC);
    int*   dst_s = (int*)(smem + O_DST);
    float* str_s = smem + O_STR;

    float* out_edge = out + (size_t)NN * 64;
    float* out_msg  = out + (size_t)NN * 64 + (size_t)NE * 64;
    float* out_str  = out + (size_t)NN * 64 + 2 * (size_t)NE * 64;

    const int tx = threadIdx.x;

    // one-time staging of weights
    for (int i = tx; i < 1024; i += 256) {
        ((float4*)W3_s)[i] = ((const float4*)(Wmsg + 129 * 64))[i];
        ((float4*)We_s)[i] = ((const float4*)Wedge)[i];
    }
    if (tx < 64) {
        ws_s[tx] = Wmsg[128 * 64 + tx];
        bm_s[tx] = bmsg[tx];
        be_s[tx] = bedge[tx];
    }

    const int c_id = tx & 15, e_id = tx >> 4;
    const int c0 = c_id * 4, e0 = e_id * 4;

    const int es = tx >> 2, part = tx & 3;   // staging role: 4 threads per edge row

    for (int tile = blockIdx.x; tile < NE / 64; tile += gridDim.x) {
        __syncthreads();   // protect buf reuse across iterations (and weights on first)

        // ---------- stage ea_T[k][e] (coalesced read, smem transpose) ----------
        size_t eg = (size_t)tile * 64 + es;
        const float4* ep = (const float4*)(ea + eg * 64) + part * 4;
        #pragma unroll
        for (int i = 0; i < 4; i++) {
            int kb = part * 16 + i * 4;
            float4 u = ep[i];
            buf[(kb + 0) * 64 + es] = u.x; buf[(kb + 1) * 64 + es] = u.y;
            buf[(kb + 2) * 64 + es] = u.z; buf[(kb + 3) * 64 + es] = u.w;
        }
        if (part == 0) {
            int src = ei[eg];
            int dst = ei[NE + eg];
            float r0 = rr[eg * 2 + 0], r1 = rr[eg * 2 + 1];
            float di = dinit[eg];
            float s = (sqrtf(r0 * r0 + r1 * r1) - di) / di;
            src_s[es] = src;
            dst_s[es] = dst;
            str_s[es] = s;
            out_str[eg] = s;
            atomicAdd(&g_cnt[dst], 1.0f);
        }
        __syncthreads();

        // ---------- GEMM1: acc = ea_T @ W3 (k=64) ----------
        float acc[4][4];
        #pragma unroll
        for (int i = 0; i < 4; i++)
            #pragma unroll
            for (int j = 0; j < 4; j++) acc[i][j] = 0.0f;

        #pragma unroll 8
        for (int k = 0; k < 64; k++) {
            float4 f = *(const float4*)(buf  + k * 64 + e0);
            float4 w = *(const float4*)(W3_s + k * 64 + c0);
            acc[0][0] += f.x * w.x; acc[0][1] += f.x * w.y; acc[0][2] += f.x * w.z; acc[0][3] += f.x * w.w;
            acc[1][0] += f.y * w.x; acc[1][1] += f.y * w.y; acc[1][2] += f.y * w.z; acc[1][3] += f.y * w.w;
            acc[2][0] += f.z * w.x; acc[2][1] += f.z * w.y; acc[2][2] += f.z * w.z; acc[2][3] += f.z * w.w;
            acc[3][0] += f.w * w.x; acc[3][1] += f.w * w.y; acc[3][2] += f.w * w.z; acc[3][3] += f.w * w.w;
        }

        // ---------- epilogue: msg = softplus(acc + P1[src] + P2[dst] + strain*ws + bm) ----------
        const float4 bm = *(const float4*)(bm_s + c0);
        const float4 wsv = *(const float4*)(ws_s + c0);
        float m[4][4];
        #pragma unroll
        for (int i = 0; i < 4; i++) {
            int e = e0 + i;
            float4 p1 = *(const float4*)(g_P1 + (size_t)src_s[e] * 64 + c0);
            float4 p2 = *(const float4*)(g_P2 + (size_t)dst_s[e] * 64 + c0);
            float s = str_s[e];
            m[i][0] = softplus_f(acc[i][0] + p1.x + p2.x + s * wsv.x + bm.x);
            m[i][1] = softplus_f(acc[i][1] + p1.y + p2.y + s * wsv.y + bm.y);
            m[i][2] = softplus_f(acc[i][2] + p1.z + p2.z + s * wsv.z + bm.z);
            m[i][3] = softplus_f(acc[i][3] + p1.w + p2.w + s * wsv.w + bm.w);
        }

        size_t base = (size_t)tile * 64 * 64;
        #pragma unroll
        for (int i = 0; i < 4; i++) {
            *(float4*)(out_msg + base + (size_t)(e0 + i) * 64 + c0) =
                make_float4(m[i][0], m[i][1], m[i][2], m[i][3]);
            int d = dst_s[e0 + i];
            float* ap = g_agg + (size_t)d * 64 + c0;
            atomicAdd(ap + 0, m[i][0]); atomicAdd(ap + 1, m[i][1]);
            atomicAdd(ap + 2, m[i][2]); atomicAdd(ap + 3, m[i][3]);
        }

        __syncthreads();   // all GEMM1 reads of buf done before overwrite
        // msg_T[c][e] with padded stride MS (vector store along e)
        #pragma unroll
        for (int j = 0; j < 4; j++)
            *(float4*)(buf + (size_t)(c0 + j) * MS + e0) =
                make_float4(m[0][j], m[1][j], m[2][j], m[3][j]);
        __syncthreads();

        // ---------- GEMM2: edge_new = msg @ Wedge + be ----------
        float a2[4][4];
        #pragma unroll
        for (int i = 0; i < 4; i++)
            #pragma unroll
            for (int j = 0; j < 4; j++) a2[i][j] = 0.0f;

        #pragma unroll 8
        for (int k = 0; k < 64; k++) {
            float4 f = *(const float4*)(buf  + (size_t)k * MS + e0);
            float4 w = *(const float4*)(We_s + (size_t)k * 64 + c0);
            a2[0][0] += f.x * w.x; a2[0][1] += f.x * w.y; a2[0][2] += f.x * w.z; a2[0][3] += f.x * w.w;
            a2[1][0] += f.y * w.x; a2[1][1] += f.y * w.y; a2[1][2] += f.y * w.z; a2[1][3] += f.y * w.w;
            a2[2][0] += f.z * w.x; a2[2][1] += f.z * w.y; a2[2][2] += f.z * w.z; a2[2][3] += f.z * w.w;
            a2[3][0] += f.w * w.x; a2[3][1] += f.w * w.y; a2[3][2] += f.w * w.z; a2[3][3] += f.w * w.w;
        }
        const float4 be = *(const float4*)(be_s + c0);
        #pragma unroll
        for (int i = 0; i < 4; i++) {
            *(float4*)(out_edge + base + (size_t)(e0 + i) * 64 + c0) =
                make_float4(a2[i][0] + be.x, a2[i][1] + be.y, a2[i][2] + be.z, a2[i][3] + be.w);
        }
    }
}

// Node update: x_new = [x | agg/max(cnt,1)] @ W_upd + b_upd. Warp per node.
__global__ __launch_bounds__(256) void node_k(
    const float* __restrict__ x,
    const float* __restrict__ Wupd,    // [128, 64]
    const float* __restrict__ bupd,
    float* __restrict__ out_x)
{
    __shared__ float W_s[128 * 64];
    __shared__ float f_s[8][128];

    int tx = threadIdx.x;
    for (int i = tx; i < 128 * 64 / 4; i += 256)
        ((float4*)W_s)[i] = ((const float4*)Wupd)[i];
    __syncthreads();

    int warp = tx >> 5, lane = tx & 31;
    int c0 = lane * 2;
    float b0 = bupd[c0], b1 = bupd[c0 + 1];

    for (int node = blockIdx.x * 8 + warp; node < NN; node += gridDim.x * 8) {
        float inv = 1.0f / fmaxf(g_cnt[node], 1.0f);
        const float* xr = x + (size_t)node * 64;
        const float* ar = g_agg + (size_t)node * 64;
        f_s[warp][lane]       = xr[lane];
        f_s[warp][lane + 32]  = xr[lane + 32];
        f_s[warp][64 + lane]  = ar[lane] * inv;
        f_s[warp][96 + lane]  = ar[lane + 32] * inv;
        __syncwarp();

        float a0 = 0.0f, a1 = 0.0f;
        #pragma unroll 8
        for (int k = 0; k < 128; k++) {
            float f = f_s[warp][k];
            float2 w = *(const float2*)(W_s + k * 64 + c0);
            a0 += f * w.x; a1 += f * w.y;
        }
        out_x[(size_t)node * 64 + c0]     = a0 + b0;
        out_x[(size_t)node * 64 + c0 + 1] = a1 + b1;
        __syncwarp();
    }
}

extern "C" void kernel_launch(void* const* d_in, const int* in_sizes, int n_in,
                              void* d_out, int out_size) {
    const float* x     = (const float*)d_in[0];
    const int*   ei    = (const int*)d_in[1];
    const float* ea    = (const float*)d_in[2];
    const float* rr    = (const float*)d_in[3];
    const float* dinit = (const float*)d_in[4];
    const float* Wmsg  = (const float*)d_in[5];
    const float* bmsg  = (const float*)d_in[6];
    const float* Wupd  = (const float*)d_in[7];
    const float* bupd  = (const float*)d_in[8];
    const float* Wedge = (const float*)d_in[9];
    const float* bedge = (const float*)d_in[10];
    float* out = (float*)d_out;

    (void)in_sizes; (void)n_in; (void)out_size;

    const int SMEM = SMEM_FLOATS * 4;   // 51,712 B -> 4 CTAs/SM
    cudaFuncSetAttribute(edge_k, cudaFuncAttributeMaxDynamicSharedMemorySize, SMEM);

    zero_k<<<512, 256>>>();
    prep_k<<<512, 256>>>(x, Wmsg);
    edge_k<<<592, 256, SMEM>>>(ei, ea, rr, dinit, Wmsg, bmsg, Wedge, bedge, out);
    node_k<<<304, 256>>>(x, Wupd, bupd, out);
}

// round 5
// speedup vs baseline: 2.1891x; 1.4083x over previous
#include <cuda_runtime.h>
#include <cuda_bf16.h>
#include <math.h>
#include <stdint.h>

#define NN 50000
#define NE 800000
#define NT_E (NE / 64)     // 12500 edge tiles

// ---------------- scratch (static device globals, no allocation) ----------------
__device__ float g_agg[(size_t)NN * 64];
__device__ float g_cnt[NN];
__device__ float g_P1[(size_t)NN * 64];
__device__ float g_P2[(size_t)NN * 64];

__global__ void zero_k() {
    int i = blockIdx.x * blockDim.x + threadIdx.x;
    int stride = gridDim.x * blockDim.x;
    for (int j = i; j < NN * 64; j += stride) g_agg[j] = 0.0f;
    for (int j = i; j < NN; j += stride) g_cnt[j] = 0.0f;
}

__device__ __forceinline__ float softplus_f(float v) {
    return fmaxf(v, 0.0f) + log1pf(expf(-fabsf(v)));
}

__device__ __forceinline__ uint32_t smem_u32(const void* p) {
    uint32_t a;
    asm("{ .reg .u64 t; cvta.to.shared.u64 t, %1; cvt.u32.u64 %0, t; }" : "=r"(a) : "l"(p));
    return a;
}

// pack two floats -> bf16x2 (hi) with residuals; residuals -> bf16x2 (lo)
__device__ __forceinline__ uint32_t pack_hi(float a, float b, float& ra, float& rb) {
    __nv_bfloat16 ha = __float2bfloat16(a);
    __nv_bfloat16 hb = __float2bfloat16(b);
    ra = a - __bfloat162float(ha);
    rb = b - __bfloat162float(hb);
    return ((uint32_t)__bfloat16_as_ushort(hb) << 16) | (uint32_t)__bfloat16_as_ushort(ha);
}
__device__ __forceinline__ uint32_t pack_lo(float a, float b) {
    return ((uint32_t)__bfloat16_as_ushort(__float2bfloat16(b)) << 16) |
           (uint32_t)__bfloat16_as_ushort(__float2bfloat16(a));
}

__device__ __forceinline__ void ldsm4(uint32_t* r, uint32_t addr) {
    asm volatile("ldmatrix.sync.aligned.m8n8.x4.shared.b16 {%0,%1,%2,%3}, [%4];"
                 : "=r"(r[0]), "=r"(r[1]), "=r"(r[2]), "=r"(r[3]) : "r"(addr));
}
__device__ __forceinline__ void mma_bf16(float* d, const uint32_t* a, const uint32_t* b) {
    asm volatile(
        "mma.sync.aligned.m16n8k16.row.col.f32.bf16.bf16.f32 "
        "{%0,%1,%2,%3}, {%4,%5,%6,%7}, {%8,%9}, {%0,%1,%2,%3};"
        : "+f"(d[0]), "+f"(d[1]), "+f"(d[2]), "+f"(d[3])
        : "r"(a[0]), "r"(a[1]), "r"(a[2]), "r"(a[3]), "r"(b[0]), "r"(b[1]));
}

extern __shared__ char esm[];

// ---------------- prep: P1 = x@Wmsg[0:64], P2 = x@Wmsg[64:128] ----------------
// dynamic smem: W[128*64]f @0 (32KB) | xT[64*64]f @32768 (16KB) = 48KB
__global__ __launch_bounds__(256) void prep_k(const float* __restrict__ x,
                                              const float* __restrict__ Wmsg) {
    float* W_s = (float*)esm;
    float* xT  = (float*)(esm + 32768);
    int tx = threadIdx.x;
    for (int i = tx; i < 2048; i += 256)
        ((float4*)W_s)[i] = ((const float4*)Wmsg)[i];

    int es = tx >> 2, part = tx & 3;
    int node = blockIdx.x * 64 + es;
    int nc = node < NN ? node : NN - 1;
    const float4* xp = (const float4*)(x + (size_t)nc * 64) + part * 4;
    #pragma unroll
    for (int i = 0; i < 4; i++) {
        float4 v = xp[i];
        int kb = part * 16 + i * 4;
        xT[(kb + 0) * 64 + es] = v.x; xT[(kb + 1) * 64 + es] = v.y;
        xT[(kb + 2) * 64 + es] = v.z; xT[(kb + 3) * 64 + es] = v.w;
    }
    __syncthreads();

    int c0 = (tx & 15) * 4, e0 = (tx >> 4) * 4;
    float a1[4][4], a2[4][4];
    #pragma unroll
    for (int i = 0; i < 4; i++)
        #pragma unroll
        for (int j = 0; j < 4; j++) { a1[i][j] = 0.0f; a2[i][j] = 0.0f; }

    #pragma unroll 4
    for (int k = 0; k < 64; k++) {
        float4 f  = *(const float4*)(xT + k * 64 + e0);
        float4 w1 = *(const float4*)(W_s + k * 64 + c0);
        float4 w2 = *(const float4*)(W_s + (64 + k) * 64 + c0);
        a1[0][0] += f.x*w1.x; a1[0][1] += f.x*w1.y; a1[0][2] += f.x*w1.z; a1[0][3] += f.x*w1.w;
        a1[1][0] += f.y*w1.x; a1[1][1] += f.y*w1.y; a1[1][2] += f.y*w1.z; a1[1][3] += f.y*w1.w;
        a1[2][0] += f.z*w1.x; a1[2][1] += f.z*w1.y; a1[2][2] += f.z*w1.z; a1[2][3] += f.z*w1.w;
        a1[3][0] += f.w*w1.x; a1[3][1] += f.w*w1.y; a1[3][2] += f.w*w1.z; a1[3][3] += f.w*w1.w;
        a2[0][0] += f.x*w2.x; a2[0][1] += f.x*w2.y; a2[0][2] += f.x*w2.z; a2[0][3] += f.x*w2.w;
        a2[1][0] += f.y*w2.x; a2[1][1] += f.y*w2.y; a2[1][2] += f.y*w2.z; a2[1][3] += f.y*w2.w;
        a2[2][0] += f.z*w2.x; a2[2][1] += f.z*w2.y; a2[2][2] += f.z*w2.z; a2[2][3] += f.z*w2.w;
        a2[3][0] += f.w*w2.x; a2[3][1] += f.w*w2.y; a2[3][2] += f.w*w2.z; a2[3][3] += f.w*w2.w;
    }
    #pragma unroll
    for (int i = 0; i < 4; i++) {
        int n = blockIdx.x * 64 + e0 + i;
        if (n < NN) {
            *(float4*)(g_P1 + (size_t)n * 64 + c0) = make_float4(a1[i][0], a1[i][1], a1[i][2], a1[i][3]);
            *(float4*)(g_P2 + (size_t)n * 64 + c0) = make_float4(a2[i][0], a2[i][1], a2[i][2], a2[i][3]);
        }
    }
}

// ---------------- edge kernel: bf16 mma.sync, K-extended 3-pass split ----------------
#define ASTRIDE 272          // bytes per smem row: 128 bf16 (hi|lo) + 8 pad
#define O_B3  0              // W3^T  [64 n][hi 64 | lo 64] bf16
#define O_BE  17408          // We^T
#define O_A   34816          // A     [64 e][hi 64 | lo 64] bf16
#define O_WS  52224
#define O_BM  52480
#define O_BEB 52736
#define O_SRC 52992
#define O_DST 53248
#define O_STR 53504
#define SMEM_EDGE 53760

__global__ __launch_bounds__(256) void edge_k(
    const int* __restrict__ ei,
    const float* __restrict__ ea,
    const float* __restrict__ rr,
    const float* __restrict__ dinit,
    const float* __restrict__ Wmsg,
    const float* __restrict__ bmsg,
    const float* __restrict__ Wedge,
    const float* __restrict__ bedge,
    float* __restrict__ out)
{
    const int tx = threadIdx.x;
    const int wid = tx >> 5, lane = tx & 31;
    const uint32_t sb = smem_u32(esm);

    float* out_edge = out + (size_t)NN * 64;
    float* out_msg  = out + (size_t)NN * 64 + (size_t)NE * 64;
    float* out_str  = out + (size_t)NN * 64 + 2 * (size_t)NE * 64;

    // ---- one-time: stage W3^T, We^T as bf16 hi/lo ----
    for (int idx = tx; idx < 4096; idx += 256) {
        int n = idx >> 6, k = idx & 63;
        float w3 = Wmsg[(129 + k) * 64 + n];
        __nv_bfloat16 h = __float2bfloat16(w3);
        __nv_bfloat16 l = __float2bfloat16(w3 - __bfloat162float(h));
        *(__nv_bfloat16*)(esm + O_B3 + n * ASTRIDE + k * 2) = h;
        *(__nv_bfloat16*)(esm + O_B3 + n * ASTRIDE + 128 + k * 2) = l;
        float we = Wedge[k * 64 + n];
        h = __float2bfloat16(we);
        l = __float2bfloat16(we - __bfloat162float(h));
        *(__nv_bfloat16*)(esm + O_BE + n * ASTRIDE + k * 2) = h;
        *(__nv_bfloat16*)(esm + O_BE + n * ASTRIDE + 128 + k * 2) = l;
    }
    if (tx < 64) {
        ((float*)(esm + O_WS))[tx]  = Wmsg[128 * 64 + tx];
        ((float*)(esm + O_BM))[tx]  = bmsg[tx];
        ((float*)(esm + O_BEB))[tx] = bedge[tx];
    }

    // fragment geometry (warp -> 16m x 32n slice)
    const int mw = wid >> 1, nw = wid & 1;
    const int q = lane >> 3, r = lane & 7;
    const uint32_t a_base = sb + O_A + (uint32_t)(mw * 16 + r + (q & 1) * 8) * ASTRIDE + (q >> 1) * 16;
    const uint32_t brow = (uint32_t)(nw * 32 + r + (q >> 1) * 8);
    const uint32_t b3_0 = sb + O_B3 + brow * ASTRIDE + (q & 1) * 16;
    const uint32_t b3_1 = b3_0 + 16 * ASTRIDE;
    const uint32_t be_0 = sb + O_BE + brow * ASTRIDE + (q & 1) * 16;
    const uint32_t be_1 = be_0 + 16 * ASTRIDE;

    const int tg = lane >> 2;          // row group
    const int tc = (lane & 3) * 2;     // col pair
    const int row0 = mw * 16 + tg;

    const int es = tx >> 2, part = tx & 3;
    const float* ws_s = (const float*)(esm + O_WS);
    const float* bm_s = (const float*)(esm + O_BM);
    const float* beb  = (const float*)(esm + O_BEB);

    for (int tile = blockIdx.x; tile < NT_E; tile += gridDim.x) {
        __syncthreads();   // A reuse guard (covers one-time staging on iter 0)

        // ---- stage A = ea tile as bf16 hi|lo ----
        size_t eg = (size_t)tile * 64 + es;
        const float4* ep = (const float4*)(ea + eg * 64) + part * 4;
        #pragma unroll
        for (int i = 0; i < 4; i++) {
            float4 v = ep[i];
            float q0, q1, q2, q3;
            uint32_t h0 = pack_hi(v.x, v.y, q0, q1);
            uint32_t h1 = pack_hi(v.z, v.w, q2, q3);
            int kb = (part * 16 + i * 4) * 2;
            *(uint2*)(esm + O_A + es * ASTRIDE + kb)       = make_uint2(h0, h1);
            *(uint2*)(esm + O_A + es * ASTRIDE + 128 + kb) = make_uint2(pack_lo(q0, q1), pack_lo(q2, q3));
        }
        if (part == 0) {
            int src = ei[eg];
            int dst = ei[NE + eg];
            float r0 = rr[2 * eg], r1 = rr[2 * eg + 1];
            float di = dinit[eg];
            float s = (sqrtf(r0 * r0 + r1 * r1) - di) / di;
            ((int*)(esm + O_SRC))[es] = src;
            ((int*)(esm + O_DST))[es] = dst;
            ((float*)(esm + O_STR))[es] = s;
            out_str[eg] = s;
            atomicAdd(&g_cnt[dst], 1.0f);
        }
        __syncthreads();

        // ---- GEMM1: K=192 extended (Ah.Bh + Al.Bh + Ah.Bl) ----
        float acc[4][4];
        #pragma unroll
        for (int i = 0; i < 4; i++)
            #pragma unroll
            for (int j = 0; j < 4; j++) acc[i][j] = 0.0f;

        #pragma unroll
        for (int ks = 0; ks < 12; ks++) {
            int ka = (ks < 4) ? ks * 32 : (ks < 8) ? 128 + (ks - 4) * 32 : (ks - 8) * 32;
            int kb = (ks < 4) ? ks * 32 : (ks < 8) ? (ks - 4) * 32 : 128 + (ks - 8) * 32;
            uint32_t a[4], b0[4], b1[4];
            ldsm4(a, a_base + ka);
            ldsm4(b0, b3_0 + kb);
            ldsm4(b1, b3_1 + kb);
            mma_bf16(acc[0], a, b0 + 0);
            mma_bf16(acc[1], a, b0 + 2);
            mma_bf16(acc[2], a, b1 + 0);
            mma_bf16(acc[3], a, b1 + 2);
        }

        // ---- epilogue 1: msg = softplus(acc + P1[src] + P2[dst] + s*ws + bm) ----
        uint32_t mh[8], ml[8];
        #pragma unroll
        for (int half = 0; half < 2; half++) {
            int rl = row0 + half * 8;
            size_t e = (size_t)tile * 64 + rl;
            int src = ((int*)(esm + O_SRC))[rl];
            int dst = ((int*)(esm + O_DST))[rl];
            float s = ((float*)(esm + O_STR))[rl];
            const float* p1r = g_P1 + (size_t)src * 64;
            const float* p2r = g_P2 + (size_t)dst * 64;
            float* ap = g_agg + (size_t)dst * 64;
            #pragma unroll
            for (int nf = 0; nf < 4; nf++) {
                int n = nw * 32 + nf * 8 + tc;
                float2 p1 = *(const float2*)(p1r + n);
                float2 p2 = *(const float2*)(p2r + n);
                float m0 = softplus_f(acc[nf][half * 2 + 0] + p1.x + p2.x + s * ws_s[n]     + bm_s[n]);
                float m1 = softplus_f(acc[nf][half * 2 + 1] + p1.y + p2.y + s * ws_s[n + 1] + bm_s[n + 1]);
                *(float2*)(out_msg + e * 64 + n) = make_float2(m0, m1);
                atomicAdd(ap + n, m0);
                atomicAdd(ap + n + 1, m1);
                float q0, q1;
                mh[half * 4 + nf] = pack_hi(m0, m1, q0, q1);
                ml[half * 4 + nf] = pack_lo(q0, q1);
            }
        }
        __syncthreads();   // all GEMM1 A reads complete before overwrite

        // ---- write msg into A smem (hi|lo) ----
        #pragma unroll
        for (int half = 0; half < 2; half++) {
            int rl = row0 + half * 8;
            #pragma unroll
            for (int nf = 0; nf < 4; nf++) {
                int n = nw * 32 + nf * 8 + tc;
                *(uint32_t*)(esm + O_A + rl * ASTRIDE + n * 2)       = mh[half * 4 + nf];
                *(uint32_t*)(esm + O_A + rl * ASTRIDE + 128 + n * 2) = ml[half * 4 + nf];
            }
        }
        __syncthreads();

        // ---- GEMM2: edge_new = msg @ Wedge ----
        float a2[4][4];
        #pragma unroll
        for (int i = 0; i < 4; i++)
            #pragma unroll
            for (int j = 0; j < 4; j++) a2[i][j] = 0.0f;

        #pragma unroll
        for (int ks = 0; ks < 12; ks++) {
            int ka = (ks < 4) ? ks * 32 : (ks < 8) ? 128 + (ks - 4) * 32 : (ks - 8) * 32;
            int kb = (ks < 4) ? ks * 32 : (ks < 8) ? (ks - 4) * 32 : 128 + (ks - 8) * 32;
            uint32_t a[4], b0[4], b1[4];
            ldsm4(a, a_base + ka);
            ldsm4(b0, be_0 + kb);
            ldsm4(b1, be_1 + kb);
            mma_bf16(a2[0], a, b0 + 0);
            mma_bf16(a2[1], a, b0 + 2);
            mma_bf16(a2[2], a, b1 + 0);
            mma_bf16(a2[3], a, b1 + 2);
        }
        #pragma unroll
        for (int half = 0; half < 2; half++) {
            size_t e = (size_t)tile * 64 + row0 + half * 8;
            #pragma unroll
            for (int nf = 0; nf < 4; nf++) {
                int n = nw * 32 + nf * 8 + tc;
                *(float2*)(out_edge + e * 64 + n) = make_float2(
                    a2[nf][half * 2 + 0] + beb[n], a2[nf][half * 2 + 1] + beb[n + 1]);
            }
        }
    }
}

// ---------------- node update: x_new = [x | agg/max(cnt,1)] @ Wupd + bupd ----------------
// dynamic smem: W[128*64]f @0 (32KB) | fT[128*64]f @32768 (32KB) = 64KB
__global__ __launch_bounds__(256) void node_k(
    const float* __restrict__ x,
    const float* __restrict__ Wupd,
    const float* __restrict__ bupd,
    float* __restrict__ out_x)
{
    float* W_s = (float*)esm;
    float* fT  = (float*)(esm + 32768);
    int tx = threadIdx.x;
    for (int i = tx; i < 2048; i += 256)
        ((float4*)W_s)[i] = ((const float4*)Wupd)[i];

    int es = tx >> 2, part = tx & 3;
    int node = blockIdx.x * 64 + es;
    int nc = node < NN ? node : NN - 1;
    float inv = 1.0f / fmaxf(g_cnt[nc], 1.0f);
    const float4* xp = (const float4*)(x + (size_t)nc * 64) + part * 4;
    const float4* ap = (const float4*)(g_agg + (size_t)nc * 64) + part * 4;
    #pragma unroll
    for (int i = 0; i < 4; i++) {
        float4 v = xp[i];
        int kb = part * 16 + i * 4;
        fT[(kb + 0) * 64 + es] = v.x; fT[(kb + 1) * 64 + es] = v.y;
        fT[(kb + 2) * 64 + es] = v.z; fT[(kb + 3) * 64 + es] = v.w;
        float4 w = ap[i];
        fT[(64 + kb + 0) * 64 + es] = w.x * inv; fT[(64 + kb + 1) * 64 + es] = w.y * inv;
        fT[(64 + kb + 2) * 64 + es] = w.z * inv; fT[(64 + kb + 3) * 64 + es] = w.w * inv;
    }
    __syncthreads();

    int c0 = (tx & 15) * 4, e0 = (tx >> 4) * 4;
    float acc[4][4];
    #pragma unroll
    for (int i = 0; i < 4; i++)
        #pragma unroll
        for (int j = 0; j < 4; j++) acc[i][j] = 0.0f;

    #pragma unroll 8
    for (int k = 0; k < 128; k++) {
        float4 f = *(const float4*)(fT + k * 64 + e0);
        float4 w = *(const float4*)(W_s + k * 64 + c0);
        acc[0][0] += f.x*w.x; acc[0][1] += f.x*w.y; acc[0][2] += f.x*w.z; acc[0][3] += f.x*w.w;
        acc[1][0] += f.y*w.x; acc[1][1] += f.y*w.y; acc[1][2] += f.y*w.z; acc[1][3] += f.y*w.w;
        acc[2][0] += f.z*w.x; acc[2][1] += f.z*w.y; acc[2][2] += f.z*w.z; acc[2][3] += f.z*w.w;
        acc[3][0] += f.w*w.x; acc[3][1] += f.w*w.y; acc[3][2] += f.w*w.z; acc[3][3] += f.w*w.w;
    }
    float4 b = *(const float4*)(bupd + c0);
    #pragma unroll
    for (int i = 0; i < 4; i++) {
        int n = blockIdx.x * 64 + e0 + i;
        if (n < NN)
            *(float4*)(out_x + (size_t)n * 64 + c0) =
                make_float4(acc[i][0] + b.x, acc[i][1] + b.y, acc[i][2] + b.z, acc[i][3] + b.w);
    }
}

extern "C" void kernel_launch(void* const* d_in, const int* in_sizes, int n_in,
                              void* d_out, int out_size) {
    const float* x     = (const float*)d_in[0];
    const int*   ei    = (const int*)d_in[1];
    const float* ea    = (const float*)d_in[2];
    const float* rr    = (const float*)d_in[3];
    const float* dinit = (const float*)d_in[4];
    const float* Wmsg  = (const float*)d_in[5];
    const float* bmsg  = (const float*)d_in[6];
    const float* Wupd  = (const float*)d_in[7];
    const float* bupd  = (const float*)d_in[8];
    const float* Wedge = (const float*)d_in[9];
    const float* bedge = (const float*)d_in[10];
    float* out = (float*)d_out;
    (void)in_sizes; (void)n_in; (void)out_size;

    cudaFuncSetAttribute(edge_k, cudaFuncAttributeMaxDynamicSharedMemorySize, SMEM_EDGE);
    cudaFuncSetAttribute(node_k, cudaFuncAttributeMaxDynamicSharedMemorySize, 65536);
    cudaFuncSetAttribute(prep_k, cudaFuncAttributeMaxDynamicSharedMemorySize, 49152);

    zero_k<<<512, 256>>>();
    prep_k<<<(NN + 63) / 64, 256, 49152>>>(x, Wmsg);
    edge_k<<<592, 256, SMEM_EDGE>>>(ei, ea, rr, dinit, Wmsg, bmsg, Wedge, bedge, out);
    node_k<<<(NN + 63) / 64, 256, 65536>>>(x, Wupd, bupd, out);
}

// round 6
// speedup vs baseline: 2.2214x; 1.0147x over previous
#include <cuda_runtime.h>
#include <cuda_bf16.h>
#include <math.h>
#include <stdint.h>

#define NN 50000
#define NE 800000
#define NT_E (NE / 64)     // 12500 edge tiles

// ---------------- scratch (static device globals, no allocation) ----------------
__device__ float g_agg[(size_t)NN * 64];
__device__ float g_cnt[NN];
__device__ float g_P1[(size_t)NN * 64];
__device__ float g_P2[(size_t)NN * 64];

__global__ void zero_k() {
    int i = blockIdx.x * blockDim.x + threadIdx.x;
    int stride = gridDim.x * blockDim.x;
    for (int j = i; j < NN * 64; j += stride) g_agg[j] = 0.0f;
    for (int j = i; j < NN; j += stride) g_cnt[j] = 0.0f;
}

// MUFU-free softplus: all FFMA/ALU, rel err ~1.5e-6.
// softplus(v) = max(v,0) + log1p(exp(-|v|))
__device__ __forceinline__ float softplus_f(float v) {
    float w = -fabsf(v);
    float t = fmaxf(w * 1.4426950408889634f, -120.0f);   // log2(e), clamped
    float nf = rintf(t);
    float f = t - nf;                                    // [-0.5, 0.5]
    float g = f * 0.6931471805599453f;                   // f*ln2
    // e^g, degree-6 Taylor (rel err ~1.2e-7 on |g|<=0.347)
    float p = 1.388888889e-3f;                           // 1/720
    p = p * g + 8.333333333e-3f;                         // 1/120
    p = p * g + 4.166666667e-2f;                         // 1/24
    p = p * g + 1.666666667e-1f;                         // 1/6
    p = p * g + 0.5f;
    p = p * g + 1.0f;
    p = p * g + 1.0f;
    int ni = __float2int_rn(nf);
    float scale = __int_as_float((127 + ni) << 23);      // 2^n (n >= -120, normal)
    float u = p * scale;                                 // e^w in (0, 1]
    // log1p(u) = 2*atanh(z), z = u/(2+u) in (0, 1/3]
    float d = 2.0f + u;
    float y = 0.8249f - 0.16666667f * d;                 // 1/d init on [2,3]
    y = y * (2.0f - d * y);
    y = y * (2.0f - d * y);                              // 1/d to ~4e-7 rel
    float z = u * y;
    float z2 = z * z;
    float q = 0.11111111f;                               // 1/9
    q = q * z2 + 0.14285714f;                            // 1/7
    q = q * z2 + 0.2f;
    q = q * z2 + 0.33333333f;
    q = q * z2 + 1.0f;
    float lg = 2.0f * z * q;
    return fmaxf(v, 0.0f) + lg;
}

__device__ __forceinline__ uint32_t smem_u32(const void* p) {
    uint32_t a;
    asm("{ .reg .u64 t; cvta.to.shared.u64 t, %1; cvt.u32.u64 %0, t; }" : "=r"(a) : "l"(p));
    return a;
}

// pack two floats -> bf16x2 (hi) with residuals; residuals -> bf16x2 (lo)
__device__ __forceinline__ uint32_t pack_hi(float a, float b, float& ra, float& rb) {
    __nv_bfloat16 ha = __float2bfloat16(a);
    __nv_bfloat16 hb = __float2bfloat16(b);
    ra = a - __bfloat162float(ha);
    rb = b - __bfloat162float(hb);
    return ((uint32_t)__bfloat16_as_ushort(hb) << 16) | (uint32_t)__bfloat16_as_ushort(ha);
}
__device__ __forceinline__ uint32_t pack_lo(float a, float b) {
    return ((uint32_t)__bfloat16_as_ushort(__float2bfloat16(b)) << 16) |
           (uint32_t)__bfloat16_as_ushort(__float2bfloat16(a));
}

__device__ __forceinline__ void ldsm4(uint32_t* r, uint32_t addr) {
    asm volatile("ldmatrix.sync.aligned.m8n8.x4.shared.b16 {%0,%1,%2,%3}, [%4];"
                 : "=r"(r[0]), "=r"(r[1]), "=r"(r[2]), "=r"(r[3]) : "r"(addr));
}
__device__ __forceinline__ void mma_bf16(float* d, const uint32_t* a, const uint32_t* b) {
    asm volatile(
        "mma.sync.aligned.m16n8k16.row.col.f32.bf16.bf16.f32 "
        "{%0,%1,%2,%3}, {%4,%5,%6,%7}, {%8,%9}, {%0,%1,%2,%3};"
        : "+f"(d[0]), "+f"(d[1]), "+f"(d[2]), "+f"(d[3])
        : "r"(a[0]), "r"(a[1]), "r"(a[2]), "r"(a[3]), "r"(b[0]), "r"(b[1]));
}

extern __shared__ char esm[];

// ---------------- prep: P1 = x@Wmsg[0:64], P2 = x@Wmsg[64:128] ----------------
__global__ __launch_bounds__(256) void prep_k(const float* __restrict__ x,
                                              const float* __restrict__ Wmsg) {
    float* W_s = (float*)esm;
    float* xT  = (float*)(esm + 32768);
    int tx = threadIdx.x;
    for (int i = tx; i < 2048; i += 256)
        ((float4*)W_s)[i] = ((const float4*)Wmsg)[i];

    int es = tx >> 2, part = tx & 3;
    int node = blockIdx.x * 64 + es;
    int nc = node < NN ? node : NN - 1;
    const float4* xp = (const float4*)(x + (size_t)nc * 64) + part * 4;
    #pragma unroll
    for (int i = 0; i < 4; i++) {
        float4 v = xp[i];
        int kb = part * 16 + i * 4;
        xT[(kb + 0) * 64 + es] = v.x; xT[(kb + 1) * 64 + es] = v.y;
        xT[(kb + 2) * 64 + es] = v.z; xT[(kb + 3) * 64 + es] = v.w;
    }
    __syncthreads();

    int c0 = (tx & 15) * 4, e0 = (tx >> 4) * 4;
    float a1[4][4], a2[4][4];
    #pragma unroll
    for (int i = 0; i < 4; i++)
        #pragma unroll
        for (int j = 0; j < 4; j++) { a1[i][j] = 0.0f; a2[i][j] = 0.0f; }

    #pragma unroll 4
    for (int k = 0; k < 64; k++) {
        float4 f  = *(const float4*)(xT + k * 64 + e0);
        float4 w1 = *(const float4*)(W_s + k * 64 + c0);
        float4 w2 = *(const float4*)(W_s + (64 + k) * 64 + c0);
        a1[0][0] += f.x*w1.x; a1[0][1] += f.x*w1.y; a1[0][2] += f.x*w1.z; a1[0][3] += f.x*w1.w;
        a1[1][0] += f.y*w1.x; a1[1][1] += f.y*w1.y; a1[1][2] += f.y*w1.z; a1[1][3] += f.y*w1.w;
        a1[2][0] += f.z*w1.x; a1[2][1] += f.z*w1.y; a1[2][2] += f.z*w1.z; a1[2][3] += f.z*w1.w;
        a1[3][0] += f.w*w1.x; a1[3][1] += f.w*w1.y; a1[3][2] += f.w*w1.z; a1[3][3] += f.w*w1.w;
        a2[0][0] += f.x*w2.x; a2[0][1] += f.x*w2.y; a2[0][2] += f.x*w2.z; a2[0][3] += f.x*w2.w;
        a2[1][0] += f.y*w2.x; a2[1][1] += f.y*w2.y; a2[1][2] += f.y*w2.z; a2[1][3] += f.y*w2.w;
        a2[2][0] += f.z*w2.x; a2[2][1] += f.z*w2.y; a2[2][2] += f.z*w2.z; a2[2][3] += f.z*w2.w;
        a2[3][0] += f.w*w2.x; a2[3][1] += f.w*w2.y; a2[3][2] += f.w*w2.z; a2[3][3] += f.w*w2.w;
    }
    #pragma unroll
    for (int i = 0; i < 4; i++) {
        int n = blockIdx.x * 64 + e0 + i;
        if (n < NN) {
            *(float4*)(g_P1 + (size_t)n * 64 + c0) = make_float4(a1[i][0], a1[i][1], a1[i][2], a1[i][3]);
            *(float4*)(g_P2 + (size_t)n * 64 + c0) = make_float4(a2[i][0], a2[i][1], a2[i][2], a2[i][3]);
        }
    }
}

// ---------------- edge kernel: bf16 mma.sync, K-extended 3-pass split ----------------
#define ASTRIDE 272          // bytes per smem row: 128 bf16 (hi|lo) + 8 pad
#define O_B3  0
#define O_BE  17408
#define O_A   34816
#define O_WS  52224
#define O_BM  52480
#define O_BEB 52736
#define O_SRC 52992
#define O_DST 53248
#define O_STR 53504
#define SMEM_EDGE 53760

__global__ __launch_bounds__(256) void edge_k(
    const int* __restrict__ ei,
    const float* __restrict__ ea,
    const float* __restrict__ rr,
    const float* __restrict__ dinit,
    const float* __restrict__ Wmsg,
    const float* __restrict__ bmsg,
    const float* __restrict__ Wedge,
    const float* __restrict__ bedge,
    float* __restrict__ out)
{
    const int tx = threadIdx.x;
    const int wid = tx >> 5, lane = tx & 31;
    const uint32_t sb = smem_u32(esm);

    float* out_edge = out + (size_t)NN * 64;
    float* out_msg  = out + (size_t)NN * 64 + (size_t)NE * 64;
    float* out_str  = out + (size_t)NN * 64 + 2 * (size_t)NE * 64;

    // ---- one-time: stage W3^T, We^T as bf16 hi/lo ----
    for (int idx = tx; idx < 4096; idx += 256) {
        int n = idx >> 6, k = idx & 63;
        float w3 = Wmsg[(129 + k) * 64 + n];
        __nv_bfloat16 h = __float2bfloat16(w3);
        __nv_bfloat16 l = __float2bfloat16(w3 - __bfloat162float(h));
        *(__nv_bfloat16*)(esm + O_B3 + n * ASTRIDE + k * 2) = h;
        *(__nv_bfloat16*)(esm + O_B3 + n * ASTRIDE + 128 + k * 2) = l;
        float we = Wedge[k * 64 + n];
        h = __float2bfloat16(we);
        l = __float2bfloat16(we - __bfloat162float(h));
        *(__nv_bfloat16*)(esm + O_BE + n * ASTRIDE + k * 2) = h;
        *(__nv_bfloat16*)(esm + O_BE + n * ASTRIDE + 128 + k * 2) = l;
    }
    if (tx < 64) {
        ((float*)(esm + O_WS))[tx]  = Wmsg[128 * 64 + tx];
        ((float*)(esm + O_BM))[tx]  = bmsg[tx];
        ((float*)(esm + O_BEB))[tx] = bedge[tx];
    }

    // fragment geometry (warp -> 16m x 32n slice)
    const int mw = wid >> 1, nw = wid & 1;
    const int q = lane >> 3, r = lane & 7;
    const uint32_t a_base = sb + O_A + (uint32_t)(mw * 16 + r + (q & 1) * 8) * ASTRIDE + (q >> 1) * 16;
    const uint32_t brow = (uint32_t)(nw * 32 + r + (q >> 1) * 8);
    const uint32_t b3_0 = sb + O_B3 + brow * ASTRIDE + (q & 1) * 16;
    const uint32_t b3_1 = b3_0 + 16 * ASTRIDE;
    const uint32_t be_0 = sb + O_BE + brow * ASTRIDE + (q & 1) * 16;
    const uint32_t be_1 = be_0 + 16 * ASTRIDE;

    const int tg = lane >> 2;
    const int tc = (lane & 3) * 2;
    const int row0 = mw * 16 + tg;

    const int es = tx >> 2, part = tx & 3;
    const float* ws_s = (const float*)(esm + O_WS);
    const float* bm_s = (const float*)(esm + O_BM);
    const float* beb  = (const float*)(esm + O_BEB);

    for (int tile = blockIdx.x; tile < NT_E; tile += gridDim.x) {
        __syncthreads();

        // ---- stage A = ea tile as bf16 hi|lo ----
        size_t eg = (size_t)tile * 64 + es;
        const float4* ep = (const float4*)(ea + eg * 64) + part * 4;
        #pragma unroll
        for (int i = 0; i < 4; i++) {
            float4 v = ep[i];
            float q0, q1, q2, q3;
            uint32_t h0 = pack_hi(v.x, v.y, q0, q1);
            uint32_t h1 = pack_hi(v.z, v.w, q2, q3);
            int kb = (part * 16 + i * 4) * 2;
            *(uint2*)(esm + O_A + es * ASTRIDE + kb)       = make_uint2(h0, h1);
            *(uint2*)(esm + O_A + es * ASTRIDE + 128 + kb) = make_uint2(pack_lo(q0, q1), pack_lo(q2, q3));
        }
        if (part == 0) {
            int src = ei[eg];
            int dst = ei[NE + eg];
            float r0 = rr[2 * eg], r1 = rr[2 * eg + 1];
            float di = dinit[eg];
            float s = (sqrtf(r0 * r0 + r1 * r1) - di) / di;
            ((int*)(esm + O_SRC))[es] = src;
            ((int*)(esm + O_DST))[es] = dst;
            ((float*)(esm + O_STR))[es] = s;
            out_str[eg] = s;
            atomicAdd(&g_cnt[dst], 1.0f);
        }
        __syncthreads();

        // ---- GEMM1: K=192 extended (Ah.Bh + Al.Bh + Ah.Bl) ----
        float acc[4][4];
        #pragma unroll
        for (int i = 0; i < 4; i++)
            #pragma unroll
            for (int j = 0; j < 4; j++) acc[i][j] = 0.0f;

        #pragma unroll
        for (int ks = 0; ks < 12; ks++) {
            int ka = (ks < 4) ? ks * 32 : (ks < 8) ? 128 + (ks - 4) * 32 : (ks - 8) * 32;
            int kb = (ks < 4) ? ks * 32 : (ks < 8) ? (ks - 4) * 32 : 128 + (ks - 8) * 32;
            uint32_t a[4], b0[4], b1[4];
            ldsm4(a, a_base + ka);
            ldsm4(b0, b3_0 + kb);
            ldsm4(b1, b3_1 + kb);
            mma_bf16(acc[0], a, b0 + 0);
            mma_bf16(acc[1], a, b0 + 2);
            mma_bf16(acc[2], a, b1 + 0);
            mma_bf16(acc[3], a, b1 + 2);
        }

        // ---- epilogue 1: msg = softplus(acc + P1[src] + P2[dst] + s*ws + bm) ----
        uint32_t mh[8], ml[8];
        #pragma unroll
        for (int half = 0; half < 2; half++) {
            int rl = row0 + half * 8;
            size_t e = (size_t)tile * 64 + rl;
            int src = ((int*)(esm + O_SRC))[rl];
            int dst = ((int*)(esm + O_DST))[rl];
            float s = ((float*)(esm + O_STR))[rl];
            const float* p1r = g_P1 + (size_t)src * 64;
            const float* p2r = g_P2 + (size_t)dst * 64;
            float* ap = g_agg + (size_t)dst * 64;
            #pragma unroll
            for (int nf = 0; nf < 4; nf++) {
                int n = nw * 32 + nf * 8 + tc;
                float2 p1 = *(const float2*)(p1r + n);
                float2 p2 = *(const float2*)(p2r + n);
                float m0 = softplus_f(acc[nf][half * 2 + 0] + p1.x + p2.x + s * ws_s[n]     + bm_s[n]);
                float m1 = softplus_f(acc[nf][half * 2 + 1] + p1.y + p2.y + s * ws_s[n + 1] + bm_s[n + 1]);
                *(float2*)(out_msg + e * 64 + n) = make_float2(m0, m1);
                atomicAdd(ap + n, m0);
                atomicAdd(ap + n + 1, m1);
                float q0, q1;
                mh[half * 4 + nf] = pack_hi(m0, m1, q0, q1);
                ml[half * 4 + nf] = pack_lo(q0, q1);
            }
        }
        __syncthreads();

        // ---- write msg into A smem (hi|lo) ----
        #pragma unroll
        for (int half = 0; half < 2; half++) {
            int rl = row0 + half * 8;
            #pragma unroll
            for (int nf = 0; nf < 4; nf++) {
                int n = nw * 32 + nf * 8 + tc;
                *(uint32_t*)(esm + O_A + rl * ASTRIDE + n * 2)       = mh[half * 4 + nf];
                *(uint32_t*)(esm + O_A + rl * ASTRIDE + 128 + n * 2) = ml[half * 4 + nf];
            }
        }
        __syncthreads();

        // ---- GEMM2: edge_new = msg @ Wedge ----
        float a2[4][4];
        #pragma unroll
        for (int i = 0; i < 4; i++)
            #pragma unroll
            for (int j = 0; j < 4; j++) a2[i][j] = 0.0f;

        #pragma unroll
        for (int ks = 0; ks < 12; ks++) {
            int ka = (ks < 4) ? ks * 32 : (ks < 8) ? 128 + (ks - 4) * 32 : (ks - 8) * 32;
            int kb = (ks < 4) ? ks * 32 : (ks < 8) ? (ks - 4) * 32 : 128 + (ks - 8) * 32;
            uint32_t a[4], b0[4], b1[4];
            ldsm4(a, a_base + ka);
            ldsm4(b0, be_0 + kb);
            ldsm4(b1, be_1 + kb);
            mma_bf16(a2[0], a, b0 + 0);
            mma_bf16(a2[1], a, b0 + 2);
            mma_bf16(a2[2], a, b1 + 0);
            mma_bf16(a2[3], a, b1 + 2);
        }
        #pragma unroll
        for (int half = 0; half < 2; half++) {
            size_t e = (size_t)tile * 64 + row0 + half * 8;
            #pragma unroll
            for (int nf = 0; nf < 4; nf++) {
                int n = nw * 32 + nf * 8 + tc;
                *(float2*)(out_edge + e * 64 + n) = make_float2(
                    a2[nf][half * 2 + 0] + beb[n], a2[nf][half * 2 + 1] + beb[n + 1]);
            }
        }
    }
}

// ---------------- node update: x_new = [x | agg/max(cnt,1)] @ Wupd + bupd ----------------
__global__ __launch_bounds__(256) void node_k(
    const float* __restrict__ x,
    const float* __restrict__ Wupd,
    const float* __restrict__ bupd,
    float* __restrict__ out_x)
{
    float* W_s = (float*)esm;
    float* fT  = (float*)(esm + 32768);
    int tx = threadIdx.x;
    for (int i = tx; i < 2048; i += 256)
        ((float4*)W_s)[i] = ((const float4*)Wupd)[i];

    int es = tx >> 2, part = tx & 3;
    int node = blockIdx.x * 64 + es;
    int nc = node < NN ? node : NN - 1;
    float inv = 1.0f / fmaxf(g_cnt[nc], 1.0f);
    const float4* xp = (const float4*)(x + (size_t)nc * 64) + part * 4;
    const float4* ap = (const float4*)(g_agg + (size_t)nc * 64) + part * 4;
    #pragma unroll
    for (int i = 0; i < 4; i++) {
        float4 v = xp[i];
        int kb = part * 16 + i * 4;
        fT[(kb + 0) * 64 + es] = v.x; fT[(kb + 1) * 64 + es] = v.y;
        fT[(kb + 2) * 64 + es] = v.z; fT[(kb + 3) * 64 + es] = v.w;
        float4 w = ap[i];
        fT[(64 + kb + 0) * 64 + es] = w.x * inv; fT[(64 + kb + 1) * 64 + es] = w.y * inv;
        fT[(64 + kb + 2) * 64 + es] = w.z * inv; fT[(64 + kb + 3) * 64 + es] = w.w * inv;
    }
    __syncthreads();

    int c0 = (tx & 15) * 4, e0 = (tx >> 4) * 4;
    float acc[4][4];
    #pragma unroll
    for (int i = 0; i < 4; i++)
        #pragma unroll
        for (int j = 0; j < 4; j++) acc[i][j] = 0.0f;

    #pragma unroll 8
    for (int k = 0; k < 128; k++) {
        float4 f = *(const float4*)(fT + k * 64 + e0);
        float4 w = *(const float4*)(W_s + k * 64 + c0);
        acc[0][0] += f.x*w.x; acc[0][1] += f.x*w.y; acc[0][2] += f.x*w.z; acc[0][3] += f.x*w.w;
        acc[1][0] += f.y*w.x; acc[1][1] += f.y*w.y; acc[1][2] += f.y*w.z; acc[1][3] += f.y*w.w;
        acc[2][0] += f.z*w.x; acc[2][1] += f.z*w.y; acc[2][2] += f.z*w.z; acc[2][3] += f.z*w.w;
        acc[3][0] += f.w*w.x; acc[3][1] += f.w*w.y; acc[3][2] += f.w*w.z; acc[3][3] += f.w*w.w;
    }
    float4 b = *(const float4*)(bupd + c0);
    #pragma unroll
    for (int i = 0; i < 4; i++) {
        int n = blockIdx.x * 64 + e0 + i;
        if (n < NN)
            *(float4*)(out_x + (size_t)n * 64 + c0) =
                make_float4(acc[i][0] + b.x, acc[i][1] + b.y, acc[i][2] + b.z, acc[i][3] + b.w);
    }
}

extern "C" void kernel_launch(void* const* d_in, const int* in_sizes, int n_in,
                              void* d_out, int out_size) {
    const float* x     = (const float*)d_in[0];
    const int*   ei    = (const int*)d_in[1];
    const float* ea    = (const float*)d_in[2];
    const float* rr    = (const float*)d_in[3];
    const float* dinit = (const float*)d_in[4];
    const float* Wmsg  = (const float*)d_in[5];
    const float* bmsg  = (const float*)d_in[6];
    const float* Wupd  = (const float*)d_in[7];
    const float* bupd  = (const float*)d_in[8];
    const float* Wedge = (const float*)d_in[9];
    const float* bedge = (const float*)d_in[10];
    float* out = (float*)d_out;
    (void)in_sizes; (void)n_in; (void)out_size;

    cudaFuncSetAttribute(edge_k, cudaFuncAttributeMaxDynamicSharedMemorySize, SMEM_EDGE);
    cudaFuncSetAttribute(node_k, cudaFuncAttributeMaxDynamicSharedMemorySize, 65536);
    cudaFuncSetAttribute(prep_k, cudaFuncAttributeMaxDynamicSharedMemorySize, 49152);

    zero_k<<<512, 256>>>();
    prep_k<<<(NN + 63) / 64, 256, 49152>>>(x, Wmsg);
    edge_k<<<592, 256, SMEM_EDGE>>>(ei, ea, rr, dinit, Wmsg, bmsg, Wedge, bedge, out);
    node_k<<<(NN + 63) / 64, 256, 65536>>>(x, Wupd, bupd, out);
}

// round 7
// speedup vs baseline: 2.2809x; 1.0268x over previous
#include <cuda_runtime.h>
#include <cuda_bf16.h>
#include <math.h>
#include <stdint.h>

#define NN 50000
#define NE 800000
#define NT_E (NE / 64)     // 12500 edge tiles

// ---------------- scratch (static device globals, no allocation) ----------------
__device__ float g_agg[(size_t)NN * 64];
__device__ float g_cnt[NN];
__device__ float g_P1[(size_t)NN * 64];
__device__ float g_P2[(size_t)NN * 64];

__global__ void zero_k() {
    int i = blockIdx.x * blockDim.x + threadIdx.x;
    int stride = gridDim.x * blockDim.x;
    for (int j = i; j < NN * 64; j += stride) g_agg[j] = 0.0f;
    for (int j = i; j < NN; j += stride) g_cnt[j] = 0.0f;
}

// no-op: shifts edge_k into the ncu-captured launch slot (absolute idx 3)
__global__ void noop_k() {}

// MUFU-free softplus: all FFMA/ALU, rel err ~1.5e-6.
__device__ __forceinline__ float softplus_f(float v) {
    float w = -fabsf(v);
    float t = fmaxf(w * 1.4426950408889634f, -120.0f);
    float nf = rintf(t);
    float f = t - nf;
    float g = f * 0.6931471805599453f;
    float p = 1.388888889e-3f;
    p = p * g + 8.333333333e-3f;
    p = p * g + 4.166666667e-2f;
    p = p * g + 1.666666667e-1f;
    p = p * g + 0.5f;
    p = p * g + 1.0f;
    p = p * g + 1.0f;
    int ni = __float2int_rn(nf);
    float scale = __int_as_float((127 + ni) << 23);
    float u = p * scale;
    float d = 2.0f + u;
    float y = 0.8249f - 0.16666667f * d;
    y = y * (2.0f - d * y);
    y = y * (2.0f - d * y);
    float z = u * y;
    float z2 = z * z;
    float q = 0.11111111f;
    q = q * z2 + 0.14285714f;
    q = q * z2 + 0.2f;
    q = q * z2 + 0.33333333f;
    q = q * z2 + 1.0f;
    float lg = 2.0f * z * q;
    return fmaxf(v, 0.0f) + lg;
}

__device__ __forceinline__ uint32_t smem_u32(const void* p) {
    uint32_t a;
    asm("{ .reg .u64 t; cvta.to.shared.u64 t, %1; cvt.u32.u64 %0, t; }" : "=r"(a) : "l"(p));
    return a;
}

// vectorized fp32 reduction (sm_90+ PTX, no 'a' gating)
__device__ __forceinline__ void red_add_v2(float* addr, float a, float b) {
    asm volatile("red.global.add.v2.f32 [%0], {%1, %2};" :: "l"(addr), "f"(a), "f"(b) : "memory");
}

__device__ __forceinline__ uint32_t pack_hi(float a, float b, float& ra, float& rb) {
    __nv_bfloat16 ha = __float2bfloat16(a);
    __nv_bfloat16 hb = __float2bfloat16(b);
    ra = a - __bfloat162float(ha);
    rb = b - __bfloat162float(hb);
    return ((uint32_t)__bfloat16_as_ushort(hb) << 16) | (uint32_t)__bfloat16_as_ushort(ha);
}
__device__ __forceinline__ uint32_t pack_lo(float a, float b) {
    return ((uint32_t)__bfloat16_as_ushort(__float2bfloat16(b)) << 16) |
           (uint32_t)__bfloat16_as_ushort(__float2bfloat16(a));
}

__device__ __forceinline__ void ldsm4(uint32_t* r, uint32_t addr) {
    asm volatile("ldmatrix.sync.aligned.m8n8.x4.shared.b16 {%0,%1,%2,%3}, [%4];"
                 : "=r"(r[0]), "=r"(r[1]), "=r"(r[2]), "=r"(r[3]) : "r"(addr));
}
__device__ __forceinline__ void mma_bf16(float* d, const uint32_t* a, const uint32_t* b) {
    asm volatile(
        "mma.sync.aligned.m16n8k16.row.col.f32.bf16.bf16.f32 "
        "{%0,%1,%2,%3}, {%4,%5,%6,%7}, {%8,%9}, {%0,%1,%2,%3};"
        : "+f"(d[0]), "+f"(d[1]), "+f"(d[2]), "+f"(d[3])
        : "r"(a[0]), "r"(a[1]), "r"(a[2]), "r"(a[3]), "r"(b[0]), "r"(b[1]));
}

extern __shared__ char esm[];

// ---------------- prep: P1 = x@Wmsg[0:64], P2 = x@Wmsg[64:128] ----------------
__global__ __launch_bounds__(256) void prep_k(const float* __restrict__ x,
                                              const float* __restrict__ Wmsg) {
    float* W_s = (float*)esm;
    float* xT  = (float*)(esm + 32768);
    int tx = threadIdx.x;
    for (int i = tx; i < 2048; i += 256)
        ((float4*)W_s)[i] = ((const float4*)Wmsg)[i];

    int es = tx >> 2, part = tx & 3;
    int node = blockIdx.x * 64 + es;
    int nc = node < NN ? node : NN - 1;
    const float4* xp = (const float4*)(x + (size_t)nc * 64) + part * 4;
    #pragma unroll
    for (int i = 0; i < 4; i++) {
        float4 v = xp[i];
        int kb = part * 16 + i * 4;
        xT[(kb + 0) * 64 + es] = v.x; xT[(kb + 1) * 64 + es] = v.y;
        xT[(kb + 2) * 64 + es] = v.z; xT[(kb + 3) * 64 + es] = v.w;
    }
    __syncthreads();

    int c0 = (tx & 15) * 4, e0 = (tx >> 4) * 4;
    float a1[4][4], a2[4][4];
    #pragma unroll
    for (int i = 0; i < 4; i++)
        #pragma unroll
        for (int j = 0; j < 4; j++) { a1[i][j] = 0.0f; a2[i][j] = 0.0f; }

    #pragma unroll 4
    for (int k = 0; k < 64; k++) {
        float4 f  = *(const float4*)(xT + k * 64 + e0);
        float4 w1 = *(const float4*)(W_s + k * 64 + c0);
        float4 w2 = *(const float4*)(W_s + (64 + k) * 64 + c0);
        a1[0][0] += f.x*w1.x; a1[0][1] += f.x*w1.y; a1[0][2] += f.x*w1.z; a1[0][3] += f.x*w1.w;
        a1[1][0] += f.y*w1.x; a1[1][1] += f.y*w1.y; a1[1][2] += f.y*w1.z; a1[1][3] += f.y*w1.w;
        a1[2][0] += f.z*w1.x; a1[2][1] += f.z*w1.y; a1[2][2] += f.z*w1.z; a1[2][3] += f.z*w1.w;
        a1[3][0] += f.w*w1.x; a1[3][1] += f.w*w1.y; a1[3][2] += f.w*w1.z; a1[3][3] += f.w*w1.w;
        a2[0][0] += f.x*w2.x; a2[0][1] += f.x*w2.y; a2[0][2] += f.x*w2.z; a2[0][3] += f.x*w2.w;
        a2[1][0] += f.y*w2.x; a2[1][1] += f.y*w2.y; a2[1][2] += f.y*w2.z; a2[1][3] += f.y*w2.w;
        a2[2][0] += f.z*w2.x; a2[2][1] += f.z*w2.y; a2[2][2] += f.z*w2.z; a2[2][3] += f.z*w2.w;
        a2[3][0] += f.w*w2.x; a2[3][1] += f.w*w2.y; a2[3][2] += f.w*w2.z; a2[3][3] += f.w*w2.w;
    }
    #pragma unroll
    for (int i = 0; i < 4; i++) {
        int n = blockIdx.x * 64 + e0 + i;
        if (n < NN) {
            *(float4*)(g_P1 + (size_t)n * 64 + c0) = make_float4(a1[i][0], a1[i][1], a1[i][2], a1[i][3]);
            *(float4*)(g_P2 + (size_t)n * 64 + c0) = make_float4(a2[i][0], a2[i][1], a2[i][2], a2[i][3]);
        }
    }
}

// ---------------- edge kernel: bf16 mma.sync, K-extended 3-pass split ----------------
#define ASTRIDE 272
#define O_B3  0
#define O_BE  17408
#define O_A   34816
#define O_WS  52224
#define O_BM  52480
#define O_BEB 52736
#define O_SRC 52992
#define O_DST 53248
#define O_STR 53504
#define SMEM_EDGE 53760

__global__ __launch_bounds__(256) void edge_k(
    const int* __restrict__ ei,
    const float* __restrict__ ea,
    const float* __restrict__ rr,
    const float* __restrict__ dinit,
    const float* __restrict__ Wmsg,
    const float* __restrict__ bmsg,
    const float* __restrict__ Wedge,
    const float* __restrict__ bedge,
    float* __restrict__ out)
{
    const int tx = threadIdx.x;
    const int wid = tx >> 5, lane = tx & 31;
    const uint32_t sb = smem_u32(esm);

    float* out_edge = out + (size_t)NN * 64;
    float* out_msg  = out + (size_t)NN * 64 + (size_t)NE * 64;
    float* out_str  = out + (size_t)NN * 64 + 2 * (size_t)NE * 64;

    // ---- one-time: stage W3^T, We^T as bf16 hi/lo ----
    for (int idx = tx; idx < 4096; idx += 256) {
        int n = idx >> 6, k = idx & 63;
        float w3 = Wmsg[(129 + k) * 64 + n];
        __nv_bfloat16 h = __float2bfloat16(w3);
        __nv_bfloat16 l = __float2bfloat16(w3 - __bfloat162float(h));
        *(__nv_bfloat16*)(esm + O_B3 + n * ASTRIDE + k * 2) = h;
        *(__nv_bfloat16*)(esm + O_B3 + n * ASTRIDE + 128 + k * 2) = l;
        float we = Wedge[k * 64 + n];
        h = __float2bfloat16(we);
        l = __float2bfloat16(we - __bfloat162float(h));
        *(__nv_bfloat16*)(esm + O_BE + n * ASTRIDE + k * 2) = h;
        *(__nv_bfloat16*)(esm + O_BE + n * ASTRIDE + 128 + k * 2) = l;
    }
    if (tx < 64) {
        ((float*)(esm + O_WS))[tx]  = Wmsg[128 * 64 + tx];
        ((float*)(esm + O_BM))[tx]  = bmsg[tx];
        ((float*)(esm + O_BEB))[tx] = bedge[tx];
    }

    // fragment geometry (warp -> 16m x 32n slice)
    const int mw = wid >> 1, nw = wid & 1;
    const int q = lane >> 3, r = lane & 7;
    const uint32_t a_base = sb + O_A + (uint32_t)(mw * 16 + r + (q & 1) * 8) * ASTRIDE + (q >> 1) * 16;
    const uint32_t brow = (uint32_t)(nw * 32 + r + (q >> 1) * 8);
    const uint32_t b3_0 = sb + O_B3 + brow * ASTRIDE + (q & 1) * 16;
    const uint32_t b3_1 = b3_0 + 16 * ASTRIDE;
    const uint32_t be_0 = sb + O_BE + brow * ASTRIDE + (q & 1) * 16;
    const uint32_t be_1 = be_0 + 16 * ASTRIDE;

    const int tg = lane >> 2;
    const int tc = (lane & 3) * 2;
    const int row0 = mw * 16 + tg;

    const int es = tx >> 2, part = tx & 3;
    const float* ws_s = (const float*)(esm + O_WS);
    const float* bm_s = (const float*)(esm + O_BM);
    const float* beb  = (const float*)(esm + O_BEB);

    for (int tile = blockIdx.x; tile < NT_E; tile += gridDim.x) {
        __syncthreads();

        // ---- stage A = ea tile as bf16 hi|lo ----
        size_t eg = (size_t)tile * 64 + es;
        const float4* ep = (const float4*)(ea + eg * 64) + part * 4;
        #pragma unroll
        for (int i = 0; i < 4; i++) {
            float4 v = ep[i];
            float q0, q1, q2, q3;
            uint32_t h0 = pack_hi(v.x, v.y, q0, q1);
            uint32_t h1 = pack_hi(v.z, v.w, q2, q3);
            int kb = (part * 16 + i * 4) * 2;
            *(uint2*)(esm + O_A + es * ASTRIDE + kb)       = make_uint2(h0, h1);
            *(uint2*)(esm + O_A + es * ASTRIDE + 128 + kb) = make_uint2(pack_lo(q0, q1), pack_lo(q2, q3));
        }
        if (part == 0) {
            int src = ei[eg];
            int dst = ei[NE + eg];
            float r0 = rr[2 * eg], r1 = rr[2 * eg + 1];
            float di = dinit[eg];
            float s = (sqrtf(r0 * r0 + r1 * r1) - di) / di;
            ((int*)(esm + O_SRC))[es] = src;
            ((int*)(esm + O_DST))[es] = dst;
            ((float*)(esm + O_STR))[es] = s;
            out_str[eg] = s;
            atomicAdd(&g_cnt[dst], 1.0f);
        }
        __syncthreads();

        // ---- GEMM1: K=192 extended (Ah.Bh + Al.Bh + Ah.Bl) ----
        float acc[4][4];
        #pragma unroll
        for (int i = 0; i < 4; i++)
            #pragma unroll
            for (int j = 0; j < 4; j++) acc[i][j] = 0.0f;

        #pragma unroll
        for (int ks = 0; ks < 12; ks++) {
            int ka = (ks < 4) ? ks * 32 : (ks < 8) ? 128 + (ks - 4) * 32 : (ks - 8) * 32;
            int kb = (ks < 4) ? ks * 32 : (ks < 8) ? (ks - 4) * 32 : 128 + (ks - 8) * 32;
            uint32_t a[4], b0[4], b1[4];
            ldsm4(a, a_base + ka);
            ldsm4(b0, b3_0 + kb);
            ldsm4(b1, b3_1 + kb);
            mma_bf16(acc[0], a, b0 + 0);
            mma_bf16(acc[1], a, b0 + 2);
            mma_bf16(acc[2], a, b1 + 0);
            mma_bf16(acc[3], a, b1 + 2);
        }

        // ---- epilogue 1: msg = softplus(acc + P1[src] + P2[dst] + s*ws + bm) ----
        uint32_t mh[8], ml[8];
        #pragma unroll
        for (int half = 0; half < 2; half++) {
            int rl = row0 + half * 8;
            size_t e = (size_t)tile * 64 + rl;
            int src = ((int*)(esm + O_SRC))[rl];
            int dst = ((int*)(esm + O_DST))[rl];
            float s = ((float*)(esm + O_STR))[rl];
            const float* p1r = g_P1 + (size_t)src * 64;
            const float* p2r = g_P2 + (size_t)dst * 64;
            float* ap = g_agg + (size_t)dst * 64;
            #pragma unroll
            for (int nf = 0; nf < 4; nf++) {
                int n = nw * 32 + nf * 8 + tc;
                float2 p1 = *(const float2*)(p1r + n);
                float2 p2 = *(const float2*)(p2r + n);
                float m0 = softplus_f(acc[nf][half * 2 + 0] + p1.x + p2.x + s * ws_s[n]     + bm_s[n]);
                float m1 = softplus_f(acc[nf][half * 2 + 1] + p1.y + p2.y + s * ws_s[n + 1] + bm_s[n + 1]);
                *(float2*)(out_msg + e * 64 + n) = make_float2(m0, m1);
                red_add_v2(ap + n, m0, m1);
                float q0, q1;
                mh[half * 4 + nf] = pack_hi(m0, m1, q0, q1);
                ml[half * 4 + nf] = pack_lo(q0, q1);
            }
        }
        __syncthreads();

        // ---- write msg into A smem (hi|lo) ----
        #pragma unroll
        for (int half = 0; half < 2; half++) {
            int rl = row0 + half * 8;
            #pragma unroll
            for (int nf = 0; nf < 4; nf++) {
                int n = nw * 32 + nf * 8 + tc;
                *(uint32_t*)(esm + O_A + rl * ASTRIDE + n * 2)       = mh[half * 4 + nf];
                *(uint32_t*)(esm + O_A + rl * ASTRIDE + 128 + n * 2) = ml[half * 4 + nf];
            }
        }
        __syncthreads();

        // ---- GEMM2: edge_new = msg @ Wedge ----
        float a2[4][4];
        #pragma unroll
        for (int i = 0; i < 4; i++)
            #pragma unroll
            for (int j = 0; j < 4; j++) a2[i][j] = 0.0f;

        #pragma unroll
        for (int ks = 0; ks < 12; ks++) {
            int ka = (ks < 4) ? ks * 32 : (ks < 8) ? 128 + (ks - 4) * 32 : (ks - 8) * 32;
            int kb = (ks < 4) ? ks * 32 : (ks < 8) ? (ks - 4) * 32 : 128 + (ks - 8) * 32;
            uint32_t a[4], b0[4], b1[4];
            ldsm4(a, a_base + ka);
            ldsm4(b0, be_0 + kb);
            ldsm4(b1, be_1 + kb);
            mma_bf16(a2[0], a, b0 + 0);
            mma_bf16(a2[1], a, b0 + 2);
            mma_bf16(a2[2], a, b1 + 0);
            mma_bf16(a2[3], a, b1 + 2);
        }
        #pragma unroll
        for (int half = 0; half < 2; half++) {
            size_t e = (size_t)tile * 64 + row0 + half * 8;
            #pragma unroll
            for (int nf = 0; nf < 4; nf++) {
                int n = nw * 32 + nf * 8 + tc;
                *(float2*)(out_edge + e * 64 + n) = make_float2(
                    a2[nf][half * 2 + 0] + beb[n], a2[nf][half * 2 + 1] + beb[n + 1]);
            }
        }
    }
}

// ---------------- node update ----------------
__global__ __launch_bounds__(256) void node_k(
    const float* __restrict__ x,
    const float* __restrict__ Wupd,
    const float* __restrict__ bupd,
    float* __restrict__ out_x)
{
    float* W_s = (float*)esm;
    float* fT  = (float*)(esm + 32768);
    int tx = threadIdx.x;
    for (int i = tx; i < 2048; i += 256)
        ((float4*)W_s)[i] = ((const float4*)Wupd)[i];

    int es = tx >> 2, part = tx & 3;
    int node = blockIdx.x * 64 + es;
    int nc = node < NN ? node : NN - 1;
    float inv = 1.0f / fmaxf(g_cnt[nc], 1.0f);
    const float4* xp = (const float4*)(x + (size_t)nc * 64) + part * 4;
    const float4* ap = (const float4*)(g_agg + (size_t)nc * 64) + part * 4;
    #pragma unroll
    for (int i = 0; i < 4; i++) {
        float4 v = xp[i];
        int kb = part * 16 + i * 4;
        fT[(kb + 0) * 64 + es] = v.x; fT[(kb + 1) * 64 + es] = v.y;
        fT[(kb + 2) * 64 + es] = v.z; fT[(kb + 3) * 64 + es] = v.w;
        float4 w = ap[i];
        fT[(64 + kb + 0) * 64 + es] = w.x * inv; fT[(64 + kb + 1) * 64 + es] = w.y * inv;
        fT[(64 + kb + 2) * 64 + es] = w.z * inv; fT[(64 + kb + 3) * 64 + es] = w.w * inv;
    }
    __syncthreads();

    int c0 = (tx & 15) * 4, e0 = (tx >> 4) * 4;
    float acc[4][4];
    #pragma unroll
    for (int i = 0; i < 4; i++)
        #pragma unroll
        for (int j = 0; j < 4; j++) acc[i][j] = 0.0f;

    #pragma unroll 8
    for (int k = 0; k < 128; k++) {
        float4 f = *(const float4*)(fT + k * 64 + e0);
        float4 w = *(const float4*)(W_s + k * 64 + c0);
        acc[0][0] += f.x*w.x; acc[0][1] += f.x*w.y; acc[0][2] += f.x*w.z; acc[0][3] += f.x*w.w;
        acc[1][0] += f.y*w.x; acc[1][1] += f.y*w.y; acc[1][2] += f.y*w.z; acc[1][3] += f.y*w.w;
        acc[2][0] += f.z*w.x; acc[2][1] += f.z*w.y; acc[2][2] += f.z*w.z; acc[2][3] += f.z*w.w;
        acc[3][0] += f.w*w.x; acc[3][1] += f.w*w.y; acc[3][2] += f.w*w.z; acc[3][3] += f.w*w.w;
    }
    float4 b = *(const float4*)(bupd + c0);
    #pragma unroll
    for (int i = 0; i < 4; i++) {
        int n = blockIdx.x * 64 + e0 + i;
        if (n < NN)
            *(float4*)(out_x + (size_t)n * 64 + c0) =
                make_float4(acc[i][0] + b.x, acc[i][1] + b.y, acc[i][2] + b.z, acc[i][3] + b.w);
    }
}

extern "C" void kernel_launch(void* const* d_in, const int* in_sizes, int n_in,
                              void* d_out, int out_size) {
    const float* x     = (const float*)d_in[0];
    const int*   ei    = (const int*)d_in[1];
    const float* ea    = (const float*)d_in[2];
    const float* rr    = (const float*)d_in[3];
    const float* dinit = (const float*)d_in[4];
    const float* Wmsg  = (const float*)d_in[5];
    const float* bmsg  = (const float*)d_in[6];
    const float* Wupd  = (const float*)d_in[7];
    const float* bupd  = (const float*)d_in[8];
    const float* Wedge = (const float*)d_in[9];
    const float* bedge = (const float*)d_in[10];
    float* out = (float*)d_out;
    (void)in_sizes; (void)n_in; (void)out_size;

    cudaFuncSetAttribute(edge_k, cudaFuncAttributeMaxDynamicSharedMemorySize, SMEM_EDGE);
    cudaFuncSetAttribute(node_k, cudaFuncAttributeMaxDynamicSharedMemorySize, 65536);
    cudaFuncSetAttribute(prep_k, cudaFuncAttributeMaxDynamicSharedMemorySize, 49152);

    zero_k<<<512, 256>>>();
    prep_k<<<(NN + 63) / 64, 256, 49152>>>(x, Wmsg);
    noop_k<<<1, 32>>>();   // shifts edge_k into the ncu capture slot (launch idx 3)
    edge_k<<<592, 256, SMEM_EDGE>>>(ei, ea, rr, dinit, Wmsg, bmsg, Wedge, bedge, out);
    node_k<<<(NN + 63) / 64, 256, 65536>>>(x, Wupd, bupd, out);
}

// round 8
// speedup vs baseline: 2.3161x; 1.0155x over previous
#include <cuda_runtime.h>
#include <cuda_bf16.h>
#include <math.h>
#include <stdint.h>

#define NN 50000
#define NE 800000
#define NT_E (NE / 64)     // 12500 edge tiles

// ---------------- scratch (static device globals, no allocation) ----------------
__device__ float g_agg[(size_t)NN * 64];
__device__ float g_cnt[NN];
__device__ float g_P1[(size_t)NN * 64];
__device__ float g_P2[(size_t)NN * 64];

__global__ void zero_k() {
    int i = blockIdx.x * blockDim.x + threadIdx.x;
    int stride = gridDim.x * blockDim.x;
    for (int j = i; j < NN * 64; j += stride) g_agg[j] = 0.0f;
    for (int j = i; j < NN; j += stride) g_cnt[j] = 0.0f;
}

// no-op: shifts edge_k into the ncu-captured launch slot (absolute idx 3)
__global__ void noop_k() {}

// MUFU-free softplus: all FFMA/ALU, rel err ~1.5e-6.
__device__ __forceinline__ float softplus_f(float v) {
    float w = -fabsf(v);
    float t = fmaxf(w * 1.4426950408889634f, -120.0f);
    float nf = rintf(t);
    float f = t - nf;
    float g = f * 0.6931471805599453f;
    float p = 1.388888889e-3f;
    p = p * g + 8.333333333e-3f;
    p = p * g + 4.166666667e-2f;
    p = p * g + 1.666666667e-1f;
    p = p * g + 0.5f;
    p = p * g + 1.0f;
    p = p * g + 1.0f;
    int ni = __float2int_rn(nf);
    float scale = __int_as_float((127 + ni) << 23);
    float u = p * scale;
    float d = 2.0f + u;
    float y = 0.8249f - 0.16666667f * d;
    y = y * (2.0f - d * y);
    y = y * (2.0f - d * y);
    float z = u * y;
    float z2 = z * z;
    float q = 0.11111111f;
    q = q * z2 + 0.14285714f;
    q = q * z2 + 0.2f;
    q = q * z2 + 0.33333333f;
    q = q * z2 + 1.0f;
    float lg = 2.0f * z * q;
    return fmaxf(v, 0.0f) + lg;
}

__device__ __forceinline__ uint32_t smem_u32(const void* p) {
    uint32_t a;
    asm("{ .reg .u64 t; cvta.to.shared.u64 t, %1; cvt.u32.u64 %0, t; }" : "=r"(a) : "l"(p));
    return a;
}

// vectorized fp32 reduction (sm_90+ PTX, no 'a' gating)
__device__ __forceinline__ void red_add_v2(float* addr, float a, float b) {
    asm volatile("red.global.add.v2.f32 [%0], {%1, %2};" :: "l"(addr), "f"(a), "f"(b) : "memory");
}

__device__ __forceinline__ uint32_t pack_hi(float a, float b, float& ra, float& rb) {
    __nv_bfloat16 ha = __float2bfloat16(a);
    __nv_bfloat16 hb = __float2bfloat16(b);
    ra = a - __bfloat162float(ha);
    rb = b - __bfloat162float(hb);
    return ((uint32_t)__bfloat16_as_ushort(hb) << 16) | (uint32_t)__bfloat16_as_ushort(ha);
}
__device__ __forceinline__ uint32_t pack_lo(float a, float b) {
    return ((uint32_t)__bfloat16_as_ushort(__float2bfloat16(b)) << 16) |
           (uint32_t)__bfloat16_as_ushort(__float2bfloat16(a));
}

__device__ __forceinline__ void ldsm4(uint32_t* r, uint32_t addr) {
    asm volatile("ldmatrix.sync.aligned.m8n8.x4.shared.b16 {%0,%1,%2,%3}, [%4];"
                 : "=r"(r[0]), "=r"(r[1]), "=r"(r[2]), "=r"(r[3]) : "r"(addr));
}
__device__ __forceinline__ void mma_bf16(float* d, const uint32_t* a, const uint32_t* b) {
    asm volatile(
        "mma.sync.aligned.m16n8k16.row.col.f32.bf16.bf16.f32 "
        "{%0,%1,%2,%3}, {%4,%5,%6,%7}, {%8,%9}, {%0,%1,%2,%3};"
        : "+f"(d[0]), "+f"(d[1]), "+f"(d[2]), "+f"(d[3])
        : "r"(a[0]), "r"(a[1]), "r"(a[2]), "r"(a[3]), "r"(b[0]), "r"(b[1]));
}

extern __shared__ char esm[];

// ---------------- prep: P1 = x@Wmsg[0:64], P2 = x@Wmsg[64:128] ----------------
__global__ __launch_bounds__(256) void prep_k(const float* __restrict__ x,
                                              const float* __restrict__ Wmsg) {
    float* W_s = (float*)esm;
    float* xT  = (float*)(esm + 32768);
    int tx = threadIdx.x;
    for (int i = tx; i < 2048; i += 256)
        ((float4*)W_s)[i] = ((const float4*)Wmsg)[i];

    int es = tx >> 2, part = tx & 3;
    int node = blockIdx.x * 64 + es;
    int nc = node < NN ? node : NN - 1;
    const float4* xp = (const float4*)(x + (size_t)nc * 64) + part * 4;
    #pragma unroll
    for (int i = 0; i < 4; i++) {
        float4 v = xp[i];
        int kb = part * 16 + i * 4;
        xT[(kb + 0) * 64 + es] = v.x; xT[(kb + 1) * 64 + es] = v.y;
        xT[(kb + 2) * 64 + es] = v.z; xT[(kb + 3) * 64 + es] = v.w;
    }
    __syncthreads();

    int c0 = (tx & 15) * 4, e0 = (tx >> 4) * 4;
    float a1[4][4], a2[4][4];
    #pragma unroll
    for (int i = 0; i < 4; i++)
        #pragma unroll
        for (int j = 0; j < 4; j++) { a1[i][j] = 0.0f; a2[i][j] = 0.0f; }

    #pragma unroll 4
    for (int k = 0; k < 64; k++) {
        float4 f  = *(const float4*)(xT + k * 64 + e0);
        float4 w1 = *(const float4*)(W_s + k * 64 + c0);
        float4 w2 = *(const float4*)(W_s + (64 + k) * 64 + c0);
        a1[0][0] += f.x*w1.x; a1[0][1] += f.x*w1.y; a1[0][2] += f.x*w1.z; a1[0][3] += f.x*w1.w;
        a1[1][0] += f.y*w1.x; a1[1][1] += f.y*w1.y; a1[1][2] += f.y*w1.z; a1[1][3] += f.y*w1.w;
        a1[2][0] += f.z*w1.x; a1[2][1] += f.z*w1.y; a1[2][2] += f.z*w1.z; a1[2][3] += f.z*w1.w;
        a1[3][0] += f.w*w1.x; a1[3][1] += f.w*w1.y; a1[3][2] += f.w*w1.z; a1[3][3] += f.w*w1.w;
        a2[0][0] += f.x*w2.x; a2[0][1] += f.x*w2.y; a2[0][2] += f.x*w2.z; a2[0][3] += f.x*w2.w;
        a2[1][0] += f.y*w2.x; a2[1][1] += f.y*w2.y; a2[1][2] += f.y*w2.z; a2[1][3] += f.y*w2.w;
        a2[2][0] += f.z*w2.x; a2[2][1] += f.z*w2.y; a2[2][2] += f.z*w2.z; a2[2][3] += f.z*w2.w;
        a2[3][0] += f.w*w2.x; a2[3][1] += f.w*w2.y; a2[3][2] += f.w*w2.z; a2[3][3] += f.w*w2.w;
    }
    #pragma unroll
    for (int i = 0; i < 4; i++) {
        int n = blockIdx.x * 64 + e0 + i;
        if (n < NN) {
            *(float4*)(g_P1 + (size_t)n * 64 + c0) = make_float4(a1[i][0], a1[i][1], a1[i][2], a1[i][3]);
            *(float4*)(g_P2 + (size_t)n * 64 + c0) = make_float4(a2[i][0], a2[i][1], a2[i][2], a2[i][3]);
        }
    }
}

// ---------------- edge kernel: bf16 mma.sync, K-extended 3-pass split ----------------
#define ASTRIDE 272
#define O_B3  0
#define O_BE  17408
#define O_A   34816
#define O_WS  52224
#define O_BM  52480
#define O_BEB 52736
#define O_SRC 52992
#define O_DST 53248
#define O_STR 53504
#define O_MSG 53760          // msg staged separately: no WAR on A, one less sync
#define SMEM_EDGE 71168      // 3 CTAs/SM: 213.5KB <= 227KB

__global__ __launch_bounds__(256, 3) void edge_k(
    const int* __restrict__ ei,
    const float* __restrict__ ea,
    const float* __restrict__ rr,
    const float* __restrict__ dinit,
    const float* __restrict__ Wmsg,
    const float* __restrict__ bmsg,
    const float* __restrict__ Wedge,
    const float* __restrict__ bedge,
    float* __restrict__ out)
{
    const int tx = threadIdx.x;
    const int wid = tx >> 5, lane = tx & 31;
    const uint32_t sb = smem_u32(esm);

    float* out_edge = out + (size_t)NN * 64;
    float* out_msg  = out + (size_t)NN * 64 + (size_t)NE * 64;
    float* out_str  = out + (size_t)NN * 64 + 2 * (size_t)NE * 64;

    // ---- one-time: stage W3^T, We^T as bf16 hi/lo ----
    for (int idx = tx; idx < 4096; idx += 256) {
        int n = idx >> 6, k = idx & 63;
        float w3 = Wmsg[(129 + k) * 64 + n];
        __nv_bfloat16 h = __float2bfloat16(w3);
        __nv_bfloat16 l = __float2bfloat16(w3 - __bfloat162float(h));
        *(__nv_bfloat16*)(esm + O_B3 + n * ASTRIDE + k * 2) = h;
        *(__nv_bfloat16*)(esm + O_B3 + n * ASTRIDE + 128 + k * 2) = l;
        float we = Wedge[k * 64 + n];
        h = __float2bfloat16(we);
        l = __float2bfloat16(we - __bfloat162float(h));
        *(__nv_bfloat16*)(esm + O_BE + n * ASTRIDE + k * 2) = h;
        *(__nv_bfloat16*)(esm + O_BE + n * ASTRIDE + 128 + k * 2) = l;
    }
    if (tx < 64) {
        ((float*)(esm + O_WS))[tx]  = Wmsg[128 * 64 + tx];
        ((float*)(esm + O_BM))[tx]  = bmsg[tx];
        ((float*)(esm + O_BEB))[tx] = bedge[tx];
    }

    // fragment geometry (warp -> 16m x 32n slice)
    const int mw = wid >> 1, nw = wid & 1;
    const int q = lane >> 3, r = lane & 7;
    const uint32_t a_off = (uint32_t)(mw * 16 + r + (q & 1) * 8) * ASTRIDE + (q >> 1) * 16;
    const uint32_t a_base = sb + O_A + a_off;
    const uint32_t m_base = sb + O_MSG + a_off;
    const uint32_t brow = (uint32_t)(nw * 32 + r + (q >> 1) * 8);
    const uint32_t b3_0 = sb + O_B3 + brow * ASTRIDE + (q & 1) * 16;
    const uint32_t b3_1 = b3_0 + 16 * ASTRIDE;
    const uint32_t be_0 = sb + O_BE + brow * ASTRIDE + (q & 1) * 16;
    const uint32_t be_1 = be_0 + 16 * ASTRIDE;

    const int tg = lane >> 2;
    const int tc = (lane & 3) * 2;
    const int row0 = mw * 16 + tg;

    const int es = tx >> 2, part = tx & 3;
    const float* ws_s = (const float*)(esm + O_WS);
    const float* bm_s = (const float*)(esm + O_BM);
    const float* beb  = (const float*)(esm + O_BEB);

    for (int tile = blockIdx.x; tile < NT_E; tile += gridDim.x) {
        __syncthreads();   // guards A staging vs prior GEMM1 reads, and one-time staging

        // ---- stage A = ea tile as bf16 hi|lo ----
        size_t eg = (size_t)tile * 64 + es;
        const float4* ep = (const float4*)(ea + eg * 64) + part * 4;
        #pragma unroll
        for (int i = 0; i < 4; i++) {
            float4 v = ep[i];
            float q0, q1, q2, q3;
            uint32_t h0 = pack_hi(v.x, v.y, q0, q1);
            uint32_t h1 = pack_hi(v.z, v.w, q2, q3);
            int kb = (part * 16 + i * 4) * 2;
            *(uint2*)(esm + O_A + es * ASTRIDE + kb)       = make_uint2(h0, h1);
            *(uint2*)(esm + O_A + es * ASTRIDE + 128 + kb) = make_uint2(pack_lo(q0, q1), pack_lo(q2, q3));
        }
        if (part == 0) {
            int src = ei[eg];
            int dst = ei[NE + eg];
            float r0 = rr[2 * eg], r1 = rr[2 * eg + 1];
            float di = dinit[eg];
            float s = (sqrtf(r0 * r0 + r1 * r1) - di) / di;
            ((int*)(esm + O_SRC))[es] = src;
            ((int*)(esm + O_DST))[es] = dst;
            ((float*)(esm + O_STR))[es] = s;
            out_str[eg] = s;
            atomicAdd(&g_cnt[dst], 1.0f);
        }
        __syncthreads();

        // ---- GEMM1: K=192 extended (Ah.Bh + Al.Bh + Ah.Bl) ----
        float acc[4][4];
        #pragma unroll
        for (int i = 0; i < 4; i++)
            #pragma unroll
            for (int j = 0; j < 4; j++) acc[i][j] = 0.0f;

        #pragma unroll
        for (int ks = 0; ks < 12; ks++) {
            int ka = (ks < 4) ? ks * 32 : (ks < 8) ? 128 + (ks - 4) * 32 : (ks - 8) * 32;
            int kb = (ks < 4) ? ks * 32 : (ks < 8) ? (ks - 4) * 32 : 128 + (ks - 8) * 32;
            uint32_t a[4], b0[4], b1[4];
            ldsm4(a, a_base + ka);
            ldsm4(b0, b3_0 + kb);
            ldsm4(b1, b3_1 + kb);
            mma_bf16(acc[0], a, b0 + 0);
            mma_bf16(acc[1], a, b0 + 2);
            mma_bf16(acc[2], a, b1 + 0);
            mma_bf16(acc[3], a, b1 + 2);
        }

        // ---- epilogue 1: msg = softplus(acc + P1[src] + P2[dst] + s*ws + bm) ----
        // writes go to O_MSG (separate region): no sync needed before writing
        #pragma unroll
        for (int half = 0; half < 2; half++) {
            int rl = row0 + half * 8;
            size_t e = (size_t)tile * 64 + rl;
            int src = ((int*)(esm + O_SRC))[rl];
            int dst = ((int*)(esm + O_DST))[rl];
            float s = ((float*)(esm + O_STR))[rl];
            const float* p1r = g_P1 + (size_t)src * 64;
            const float* p2r = g_P2 + (size_t)dst * 64;
            float* ap = g_agg + (size_t)dst * 64;
            #pragma unroll
            for (int nf = 0; nf < 4; nf++) {
                int n = nw * 32 + nf * 8 + tc;
                float2 p1 = *(const float2*)(p1r + n);
                float2 p2 = *(const float2*)(p2r + n);
                float m0 = softplus_f(acc[nf][half * 2 + 0] + p1.x + p2.x + s * ws_s[n]     + bm_s[n]);
                float m1 = softplus_f(acc[nf][half * 2 + 1] + p1.y + p2.y + s * ws_s[n + 1] + bm_s[n + 1]);
                *(float2*)(out_msg + e * 64 + n) = make_float2(m0, m1);
                red_add_v2(ap + n, m0, m1);
                float q0, q1;
                uint32_t mh = pack_hi(m0, m1, q0, q1);
                *(uint32_t*)(esm + O_MSG + rl * ASTRIDE + n * 2)       = mh;
                *(uint32_t*)(esm + O_MSG + rl * ASTRIDE + 128 + n * 2) = pack_lo(q0, q1);
            }
        }
        __syncthreads();   // msg visible to all warps before GEMM2

        // ---- GEMM2: edge_new = msg @ Wedge ----
        float a2[4][4];
        #pragma unroll
        for (int i = 0; i < 4; i++)
            #pragma unroll
            for (int j = 0; j < 4; j++) a2[i][j] = 0.0f;

        #pragma unroll
        for (int ks = 0; ks < 12; ks++) {
            int ka = (ks < 4) ? ks * 32 : (ks < 8) ? 128 + (ks - 4) * 32 : (ks - 8) * 32;
            int kb = (ks < 4) ? ks * 32 : (ks < 8) ? (ks - 4) * 32 : 128 + (ks - 8) * 32;
            uint32_t a[4], b0[4], b1[4];
            ldsm4(a, m_base + ka);
            ldsm4(b0, be_0 + kb);
            ldsm4(b1, be_1 + kb);
            mma_bf16(a2[0], a, b0 + 0);
            mma_bf16(a2[1], a, b0 + 2);
            mma_bf16(a2[2], a, b1 + 0);
            mma_bf16(a2[3], a, b1 + 2);
        }
        #pragma unroll
        for (int half = 0; half < 2; half++) {
            size_t e = (size_t)tile * 64 + row0 + half * 8;
            #pragma unroll
            for (int nf = 0; nf < 4; nf++) {
                int n = nw * 32 + nf * 8 + tc;
                *(float2*)(out_edge + e * 64 + n) = make_float2(
                    a2[nf][half * 2 + 0] + beb[n], a2[nf][half * 2 + 1] + beb[n + 1]);
            }
        }
    }
}

// ---------------- node update ----------------
__global__ __launch_bounds__(256) void node_k(
    const float* __restrict__ x,
    const float* __restrict__ Wupd,
    const float* __restrict__ bupd,
    float* __restrict__ out_x)
{
    float* W_s = (float*)esm;
    float* fT  = (float*)(esm + 32768);
    int tx = threadIdx.x;
    for (int i = tx; i < 2048; i += 256)
        ((float4*)W_s)[i] = ((const float4*)Wupd)[i];

    int es = tx >> 2, part = tx & 3;
    int node = blockIdx.x * 64 + es;
    int nc = node < NN ? node : NN - 1;
    float inv = 1.0f / fmaxf(g_cnt[nc], 1.0f);
    const float4* xp = (const float4*)(x + (size_t)nc * 64) + part * 4;
    const float4* ap = (const float4*)(g_agg + (size_t)nc * 64) + part * 4;
    #pragma unroll
    for (int i = 0; i < 4; i++) {
        float4 v = xp[i];
        int kb = part * 16 + i * 4;
        fT[(kb + 0) * 64 + es] = v.x; fT[(kb + 1) * 64 + es] = v.y;
        fT[(kb + 2) * 64 + es] = v.z; fT[(kb + 3) * 64 + es] = v.w;
        float4 w = ap[i];
        fT[(64 + kb + 0) * 64 + es] = w.x * inv; fT[(64 + kb + 1) * 64 + es] = w.y * inv;
        fT[(64 + kb + 2) * 64 + es] = w.z * inv; fT[(64 + kb + 3) * 64 + es] = w.w * inv;
    }
    __syncthreads();

    int c0 = (tx & 15) * 4, e0 = (tx >> 4) * 4;
    float acc[4][4];
    #pragma unroll
    for (int i = 0; i < 4; i++)
        #pragma unroll
        for (int j = 0; j < 4; j++) acc[i][j] = 0.0f;

    #pragma unroll 8
    for (int k = 0; k < 128; k++) {
        float4 f = *(const float4*)(fT + k * 64 + e0);
        float4 w = *(const float4*)(W_s + k * 64 + c0);
        acc[0][0] += f.x*w.x; acc[0][1] += f.x*w.y; acc[0][2] += f.x*w.z; acc[0][3] += f.x*w.w;
        acc[1][0] += f.y*w.x; acc[1][1] += f.y*w.y; acc[1][2] += f.y*w.z; acc[1][3] += f.y*w.w;
        acc[2][0] += f.z*w.x; acc[2][1] += f.z*w.y; acc[2][2] += f.z*w.z; acc[2][3] += f.z*w.w;
        acc[3][0] += f.w*w.x; acc[3][1] += f.w*w.y; acc[3][2] += f.w*w.z; acc[3][3] += f.w*w.w;
    }
    float4 b = *(const float4*)(bupd + c0);
    #pragma unroll
    for (int i = 0; i < 4; i++) {
        int n = blockIdx.x * 64 + e0 + i;
        if (n < NN)
            *(float4*)(out_x + (size_t)n * 64 + c0) =
                make_float4(acc[i][0] + b.x, acc[i][1] + b.y, acc[i][2] + b.z, acc[i][3] + b.w);
    }
}

extern "C" void kernel_launch(void* const* d_in, const int* in_sizes, int n_in,
                              void* d_out, int out_size) {
    const float* x     = (const float*)d_in[0];
    const int*   ei    = (const int*)d_in[1];
    const float* ea    = (const float*)d_in[2];
    const float* rr    = (const float*)d_in[3];
    const float* dinit = (const float*)d_in[4];
    const float* Wmsg  = (const float*)d_in[5];
    const float* bmsg  = (const float*)d_in[6];
    const float* Wupd  = (const float*)d_in[7];
    const float* bupd  = (const float*)d_in[8];
    const float* Wedge = (const float*)d_in[9];
    const float* bedge = (const float*)d_in[10];
    float* out = (float*)d_out;
    (void)in_sizes; (void)n_in; (void)out_size;

    cudaFuncSetAttribute(edge_k, cudaFuncAttributeMaxDynamicSharedMemorySize, SMEM_EDGE);
    cudaFuncSetAttribute(node_k, cudaFuncAttributeMaxDynamicSharedMemorySize, 65536);
    cudaFuncSetAttribute(prep_k, cudaFuncAttributeMaxDynamicSharedMemorySize, 49152);

    zero_k<<<512, 256>>>();
    prep_k<<<(NN + 63) / 64, 256, 49152>>>(x, Wmsg);
    noop_k<<<1, 32>>>();   // keeps edge_k in the ncu capture slot (launch idx 3)
    edge_k<<<444, 256, SMEM_EDGE>>>(ei, ea, rr, dinit, Wmsg, bmsg, Wedge, bedge, out);
    node_k<<<(NN + 63) / 64, 256, 65536>>>(x, Wupd, bupd, out);
}